// round 3
// baseline (speedup 1.0000x reference)
#include <cuda_runtime.h>

// S4 DPLR layer, round 3: radix-4 Stockham, fused kernels, fast twiddles.
// (Round-2 NaN fix: atRoots Omega uses sincosf so 1+Omega never becomes
//  exactly 0 at the Nyquist index — matches the float32 reference behavior.)
//
// Pipeline (5 kernels):
//  k1: generate atRoots (DPLR) directly per (row k1, col m), row IFFT512,
//      inter-pass twiddle  -> dB          [IFFT_L pass 1 + generator fused]
//  k2: column IFFT512 of dB -> dK (= K, real, scaled 1/L)   [IFFT_L pass 2]
//  k3: column FFT512 of z = u + i*K (zero-padded), fwd twiddle -> dA
//  k4: MEGA: paired rows (k1, 512-k1): fwd FFT1024 x2, Hermitian split
//      U,Kd + multiply, inv FFT1024 x2, inv twiddle -> dB
//  k5: column IFFT512 of dB, emit out[n] = Re/2L + D*u[n]  (first L only)

#define L_SIZE   262144   // 2^18
#define N2L      524288   // 2^19
#define PI2      6.283185307179586f

__device__ float2 dA[N2L];    // 4 MB scratch
__device__ float2 dB[N2L];    // 4 MB scratch
__device__ float  dK[L_SIZE]; // 1 MB kernel K

static __device__ __forceinline__ float2 cmul(float2 a, float2 b) {
    return make_float2(a.x*b.x - a.y*b.y, a.x*b.y + a.y*b.x);
}
static __device__ __forceinline__ float2 cfma(float2 a, float2 b, float2 acc) {
    acc.x = fmaf(a.x, b.x, fmaf(-a.y, b.y, acc.x));
    acc.y = fmaf(a.x, b.y, fmaf( a.y, b.x, acc.y));
    return acc;
}

// Table: tw[k] = exp(-2*pi*i*k/len), k in [0, len/2).  (forward sign baked)
template<int NT>
static __device__ __forceinline__ void fill_tw(float2* tw, int half, int len) {
    for (int k = threadIdx.x; k < half; k += NT) {
        float s, c;
        sincospif(-2.0f * (float)k / (float)len, &s, &c);
        tw[k] = make_float2(c, s);
    }
}

// exp(sgn * 2*pi*i * mm / n), mm in [0, n). Centered arg -> __sincosf safe.
static __device__ __forceinline__ float2 twiddle_c(int mm, int n, float sgn) {
    int tt = mm - ((mm >= (n >> 1)) ? n : 0);
    float ang = sgn * (PI2 / (float)n) * (float)tt;
    float s, c; __sincosf(ang, &s, &c);
    return make_float2(c, s);
}

// Radix-4 Stockham (radix-2 first stage when LOG odd). NFFT batched length-LEN
// FFTs in smem; batch g at x[g*LEN + i]. Natural-order I/O. Table tw is
// forward-signed; SIGN=-1 forward, SIGN=+1 inverse (conjugates table).
template<int LEN, int LOG, int NFFT, int SIGN, int NT>
static __device__ __forceinline__ float2* stockham4(float2* x, float2* y, const float2* tw) {
    constexpr int H = LEN >> 1, Q = LEN >> 2;
    int s = 1;
    if (LOG & 1) {
        __syncthreads();
        for (int bi = threadIdx.x; bi < NFFT * H; bi += NT) {
            const int g = bi >> (LOG - 1);
            const int p = bi & (H - 1);
            const int base = g * LEN;
            float2 a = x[base + p], c = x[base + p + H];
            float2 w = tw[p]; if (SIGN > 0) w.y = -w.y;
            y[base + 2*p]     = make_float2(a.x + c.x, a.y + c.y);
            y[base + 2*p + 1] = cmul(make_float2(a.x - c.x, a.y - c.y), w);
        }
        { float2* tp = x; x = y; y = tp; }
        s = 2;
    }
    while (s < LEN) {
        __syncthreads();
        for (int bi = threadIdx.x; bi < NFFT * Q; bi += NT) {
            const int g  = bi >> (LOG - 2);
            const int b  = bi & (Q - 1);
            const int q  = b & (s - 1);
            const int ps = b - q;
            const int ib = g * LEN + q;
            float2 x0 = x[ib + ps];
            float2 x1 = x[ib + ps + Q];
            float2 x2 = x[ib + ps + 2*Q];
            float2 x3 = x[ib + ps + 3*Q];
            float2 w1 = tw[ps], w2 = tw[2*ps];
            if (SIGN > 0) { w1.y = -w1.y; w2.y = -w2.y; }
            float2 w3 = cmul(w1, w2);
            float2 e0 = make_float2(x0.x + x2.x, x0.y + x2.y);
            float2 e1 = make_float2(x0.x - x2.x, x0.y - x2.y);
            float2 o0 = make_float2(x1.x + x3.x, x1.y + x3.y);
            float2 d  = make_float2(x1.x - x3.x, x1.y - x3.y);
            float2 o1 = (SIGN > 0) ? make_float2(-d.y, d.x)   // +i*d
                                   : make_float2( d.y, -d.x); // -i*d
            const int ob = g * LEN + q + 4*ps;
            y[ob]       = make_float2(e0.x + o0.x, e0.y + o0.y);
            y[ob + s]   = cmul(make_float2(e1.x + o1.x, e1.y + o1.y), w1);
            y[ob + 2*s] = cmul(make_float2(e0.x - o0.x, e0.y - o0.y), w2);
            y[ob + 3*s] = cmul(make_float2(e1.x - o1.x, e1.y - o1.y), w3);
        }
        { float2* tp = x; x = y; y = tp; }
        s <<= 2;
    }
    __syncthreads();
    return x;
}

// DPLR generating-function value at root index j.
// NOTE: uses sincosf (NOT sincospif) for Omega: float-pi inexactness keeps
// 1+Omega != 0 at j = L/2, exactly mirroring the float32 JAX reference.
static __device__ __forceinline__ float2 atroots_val(
    int j, float step,
    const float* sLre, const float* sLim,
    const float2* sv0, const float2* sv1, const float2* sv2, const float2* sv3)
{
    float ang = -PI2 * ((float)j / (float)L_SIZE);
    float sn, cs; sincosf(ang, &sn, &cs);          // Omega = cs + i*sn
    float2 onem = make_float2(1.f - cs, -sn);
    float2 onep = make_float2(1.f + cs,  sn);
    float invp = 1.f / (onep.x*onep.x + onep.y*onep.y);
    float2 cc = make_float2(2.f*onep.x*invp, -2.f*onep.y*invp);
    float2 qv = cmul(onem, make_float2(onep.x, -onep.y));
    float sfac = (2.f / step) * invp;
    float gx = qv.x * sfac, gy = qv.y * sfac;
    float2 k00 = {0,0}, k01 = {0,0}, k10 = {0,0}, k11 = {0,0};
    #pragma unroll
    for (int n = 0; n < 64; ++n) {
        float dx = gx - sLre[n], dy = gy - sLim[n];
        float inv = 1.f / (dx*dx + dy*dy);
        float2 r = make_float2(dx*inv, -dy*inv);
        k00 = cfma(r, sv0[n], k00);
        k01 = cfma(r, sv1[n], k01);
        k10 = cfma(r, sv2[n], k10);
        k11 = cfma(r, sv3[n], k11);
    }
    float2 den = make_float2(1.f + k11.x, k11.y);
    float invd = 1.f / (den.x*den.x + den.y*den.y);
    float2 num = cmul(k01, k10);
    float2 tq  = cmul(num, make_float2(den.x*invd, -den.y*invd));
    return cmul(cc, make_float2(k00.x - tq.x, k00.y - tq.y));
}

// ---------------------------------------------------------------------------
// k1: atRoots generator + IFFT_L row pass (len 512) + twiddle -> dB
//     row k1 holds atRoots[j], j = k1 + 512*m. grid=256 (2 rows/block)
// ---------------------------------------------------------------------------
#define TPB1 256
__global__ void k1_gen_rowfft(const float* __restrict__ Lre, const float* __restrict__ Lim,
                              const float* __restrict__ Pre, const float* __restrict__ Pim,
                              const float* __restrict__ Bre, const float* __restrict__ Bim,
                              const float* __restrict__ Cri, const float* __restrict__ ls) {
    __shared__ float2 s0[1024], s1[1024], tw[256];
    __shared__ float  sLre[64], sLim[64];
    __shared__ float2 sv0[64], sv1[64], sv2[64], sv3[64];
    const int t = threadIdx.x;
    if (t < 64) {
        float2 Pv = make_float2(Pre[t], Pim[t]);
        float2 Bv = make_float2(Bre[t], Bim[t]);
        float2 Cj = make_float2(Cri[2*t], -Cri[2*t+1]);
        float2 Pj = make_float2(Pv.x, -Pv.y);
        sLre[t] = Lre[t]; sLim[t] = Lim[t];
        sv0[t] = cmul(Cj, Bv); sv1[t] = cmul(Cj, Pv);
        sv2[t] = cmul(Pj, Bv); sv3[t] = cmul(Pj, Pv);
    }
    fill_tw<TPB1>(tw, 256, 512);
    __syncthreads();

    const int row0 = blockIdx.x * 2;
    const float step = expf(ls[0]);
    for (int i = t; i < 1024; i += TPB1) {
        int g = i >> 9, m = i & 511;
        int j = (row0 + g) + (m << 9);
        s0[i] = atroots_val(j, step, sLre, sLim, sv0, sv1, sv2, sv3);
    }
    float2* r = stockham4<512, 9, 2, +1, TPB1>(s0, s1, tw);
    for (int i = t; i < 1024; i += TPB1) {
        int g = i >> 9, m = i & 511;
        int kk = row0 + g;
        int mm = (m * kk) & (L_SIZE - 1);
        dB[kk * 512 + m] = cmul(r[i], twiddle_c(mm, L_SIZE, 1.0f));
    }
}

// ---------------------------------------------------------------------------
// k2: IFFT_L column pass (len 512, 2 cols/block) -> dK. grid=256
// ---------------------------------------------------------------------------
#define TPB2 256
__global__ void k2_ifft_cols() {
    __shared__ float2 s0[1024], s1[1024], tw[256];
    fill_tw<TPB2>(tw, 256, 512);
    const int c0 = blockIdx.x * 2;
    for (int i = threadIdx.x; i < 1024; i += TPB2) {
        int g = i & 1, rr = i >> 1;
        s0[g * 512 + rr] = dB[rr * 512 + c0 + g];
    }
    float2* r = stockham4<512, 9, 2, +1, TPB2>(s0, s1, tw);
    const float invL = 1.0f / (float)L_SIZE;
    for (int i = threadIdx.x; i < 1024; i += TPB2) {
        int g = i & 1, p = i >> 1;
        dK[p * 512 + c0 + g] = r[g * 512 + p].x * invL;
    }
}

// ---------------------------------------------------------------------------
// k3: forward column FFTs (len 512) of z = u + i*K (zero-padded), + fwd
//     twiddle, write dA[k1*1024 + c]. 2 cols/block, grid=512
// ---------------------------------------------------------------------------
#define TPB3 256
__global__ void k3_fwd_cols(const float* __restrict__ u) {
    __shared__ float2 s0[1024], s1[1024], tw[256];
    fill_tw<TPB3>(tw, 256, 512);
    const int c0 = blockIdx.x * 2;
    for (int i = threadIdx.x; i < 1024; i += TPB3) {
        int g = i & 1, rr = i >> 1;
        float2 z = make_float2(0.f, 0.f);
        if (rr < 256) {
            int idx = rr * 1024 + c0 + g;
            z = make_float2(u[idx], dK[idx]);
        }
        s0[g * 512 + rr] = z;
    }
    float2* r = stockham4<512, 9, 2, -1, TPB3>(s0, s1, tw);
    for (int i = threadIdx.x; i < 1024; i += TPB3) {
        int g = i & 1, k1 = i >> 1;
        int c = c0 + g;
        int mm = (c * k1) & (N2L - 1);
        dA[k1 * 1024 + c] = cmul(r[g * 512 + k1], twiddle_c(mm, N2L, -1.0f));
    }
}

// ---------------------------------------------------------------------------
// k4 MEGA: paired rows (k1, 512-k1); block 0 takes self-paired rows {0, 256}.
//   fwd FFT1024 x2 -> Z; Hermitian split U,Kd + multiply -> Y;
//   inv FFT1024 x2 on Y; inv twiddle; write dB[k1*1024 + m]. grid=256
// ---------------------------------------------------------------------------
#define TPB4 512
__global__ void k4_mega() {
    __shared__ float2 s0[2048], s1[2048], tw[512];
    fill_tw<TPB4>(tw, 512, 1024);
    const int b = blockIdx.x;
    const int rowA = b;                       // b=0 -> row 0
    const int rowB = (b == 0) ? 256 : 512 - b;
    const int t = threadIdx.x;

    for (int i = t; i < 2048; i += TPB4) {
        int slot = i >> 10, m = i & 1023;
        int row = slot ? rowB : rowA;
        s0[i] = dA[row * 1024 + m];
    }
    float2* Z = stockham4<1024, 10, 2, -1, TPB4>(s0, s1, tw);
    float2* Y = (Z == s0) ? s1 : s0;

    // Pointwise: Y = U * Kd from Z and Hermitian partner.
    for (int i = t; i < 2048; i += TPB4) {
        int slot = i >> 10, k2 = i & 1023;
        float2 Zv = Z[i];
        float2 Zp;
        if (b == 0) {
            int pk2 = slot ? (1023 - k2) : ((1024 - k2) & 1023);
            Zp = Z[(slot << 10) + pk2];
        } else {
            Zp = Z[((1 - slot) << 10) + (1023 - k2)];
        }
        float2 U  = make_float2(0.5f * (Zv.x + Zp.x),  0.5f * (Zv.y - Zp.y));
        float2 Kd = make_float2(0.5f * (Zv.y + Zp.y), -0.5f * (Zv.x - Zp.x));
        Y[i] = cmul(U, Kd);
    }
    float2* r = stockham4<1024, 10, 2, +1, TPB4>(Y, Z, tw);
    for (int i = t; i < 2048; i += TPB4) {
        int slot = i >> 10, m = i & 1023;
        int kk = slot ? rowB : rowA;
        int mm = (m * kk) & (N2L - 1);
        dB[kk * 1024 + m] = cmul(r[i], twiddle_c(mm, N2L, 1.0f));
    }
}

// ---------------------------------------------------------------------------
// k5: inverse column FFTs (len 512, 2 cols/block); out[n] = Re/2L + D*u[n],
//     only first 256 rows (n < L). grid=512
// ---------------------------------------------------------------------------
#define TPB5 256
__global__ void k5_inv_cols(const float* __restrict__ u, const float* __restrict__ Dp,
                            float* __restrict__ out) {
    __shared__ float2 s0[1024], s1[1024], tw[256];
    fill_tw<TPB5>(tw, 256, 512);
    const int c0 = blockIdx.x * 2;
    for (int i = threadIdx.x; i < 1024; i += TPB5) {
        int g = i & 1, rr = i >> 1;
        s0[g * 512 + rr] = dB[rr * 1024 + c0 + g];
    }
    float2* r = stockham4<512, 9, 2, +1, TPB5>(s0, s1, tw);
    const float sc = 1.0f / (float)N2L;
    const float Dv = Dp[0];
    for (int i = threadIdx.x; i < 512; i += TPB5) {
        int g = i & 1, p = i >> 1;
        int n = p * 1024 + c0 + g;
        out[n] = fmaf(Dv, u[n], r[g * 512 + p].x * sc);
    }
}

// ---------------------------------------------------------------------------
extern "C" void kernel_launch(void* const* d_in, const int* in_sizes, int n_in,
                              void* d_out, int out_size) {
    (void)in_sizes; (void)n_in; (void)out_size;
    const float* u   = (const float*)d_in[0];
    const float* Lre = (const float*)d_in[1];
    const float* Lim = (const float*)d_in[2];
    const float* Pre = (const float*)d_in[3];
    const float* Pim = (const float*)d_in[4];
    const float* Bre = (const float*)d_in[5];
    const float* Bim = (const float*)d_in[6];
    const float* Cri = (const float*)d_in[7];
    const float* Dp  = (const float*)d_in[8];
    const float* ls  = (const float*)d_in[9];
    float* out = (float*)d_out;

    k1_gen_rowfft<<<256, TPB1>>>(Lre, Lim, Pre, Pim, Bre, Bim, Cri, ls);
    k2_ifft_cols <<<256, TPB2>>>();
    k3_fwd_cols  <<<512, TPB3>>>(u);
    k4_mega      <<<256, TPB4>>>();
    k5_inv_cols  <<<512, TPB5>>>(u, Dp, out);
}

// round 4
// speedup vs baseline: 1.6056x; 1.6056x over previous
#include <cuda_runtime.h>

// S4 DPLR layer, round 4: radix-4 Stockham FFTs + standalone generator.
// (R3 regression root-caused: generator fused into the FFT kernel serialized
//  4 roots/thread under a giant unrolled body -> I$ thrash at grid=256.
//  Generator is back to its own kernel, one root per thread, grid=1024.)
//
// Pipeline (6 kernels):
//  k0: DPLR generator: atRoots[j] -> dA[(j mod 512)*512 + (j div 512)]
//  k1: row IFFT512 of dA + inter-pass twiddle -> dB     [IFFT_L pass 1]
//  k2: column IFFT512 of dB -> dK (= K, real, scaled 1/L)  [IFFT_L pass 2]
//  k3: column FFT512 of z = u + i*K (zero-padded), fwd twiddle -> dA
//  k4: MEGA: paired rows (k1, 512-k1): fwd FFT1024 x2, Hermitian split
//      U,Kd + multiply, inv FFT1024 x2, inv twiddle -> dB
//  k5: column IFFT512 of dB, emit out[n] = Re/2L + D*u[n]  (first L only)

#define L_SIZE   262144   // 2^18
#define N2L      524288   // 2^19
#define PI2      6.283185307179586f

__device__ float2 dA[N2L];    // 4 MB scratch
__device__ float2 dB[N2L];    // 4 MB scratch
__device__ float  dK[L_SIZE]; // 1 MB kernel K

static __device__ __forceinline__ float2 cmul(float2 a, float2 b) {
    return make_float2(a.x*b.x - a.y*b.y, a.x*b.y + a.y*b.x);
}
static __device__ __forceinline__ float2 cfma(float2 a, float2 b, float2 acc) {
    acc.x = fmaf(a.x, b.x, fmaf(-a.y, b.y, acc.x));
    acc.y = fmaf(a.x, b.y, fmaf( a.y, b.x, acc.y));
    return acc;
}

// Table: tw[k] = exp(-2*pi*i*k/len), k in [0, len/2).  (forward sign baked)
template<int NT>
static __device__ __forceinline__ void fill_tw(float2* tw, int half, int len) {
    for (int k = threadIdx.x; k < half; k += NT) {
        float s, c;
        sincospif(-2.0f * (float)k / (float)len, &s, &c);
        tw[k] = make_float2(c, s);
    }
}

// exp(sgn * 2*pi*i * mm / n), mm in [0, n). Centered arg -> __sincosf safe.
static __device__ __forceinline__ float2 twiddle_c(int mm, int n, float sgn) {
    int tt = mm - ((mm >= (n >> 1)) ? n : 0);
    float ang = sgn * (PI2 / (float)n) * (float)tt;
    float s, c; __sincosf(ang, &s, &c);
    return make_float2(c, s);
}

// Radix-4 Stockham (radix-2 first stage when LOG odd). NFFT batched length-LEN
// FFTs in smem; batch g at x[g*LEN + i]. Natural-order I/O. Table tw is
// forward-signed; SIGN=-1 forward, SIGN=+1 inverse (conjugates table).
template<int LEN, int LOG, int NFFT, int SIGN, int NT>
static __device__ __forceinline__ float2* stockham4(float2* x, float2* y, const float2* tw) {
    constexpr int H = LEN >> 1, Q = LEN >> 2;
    int s = 1;
    if (LOG & 1) {
        __syncthreads();
        for (int bi = threadIdx.x; bi < NFFT * H; bi += NT) {
            const int g = bi >> (LOG - 1);
            const int p = bi & (H - 1);
            const int base = g * LEN;
            float2 a = x[base + p], c = x[base + p + H];
            float2 w = tw[p]; if (SIGN > 0) w.y = -w.y;
            y[base + 2*p]     = make_float2(a.x + c.x, a.y + c.y);
            y[base + 2*p + 1] = cmul(make_float2(a.x - c.x, a.y - c.y), w);
        }
        { float2* tp = x; x = y; y = tp; }
        s = 2;
    }
    while (s < LEN) {
        __syncthreads();
        for (int bi = threadIdx.x; bi < NFFT * Q; bi += NT) {
            const int g  = bi >> (LOG - 2);
            const int b  = bi & (Q - 1);
            const int q  = b & (s - 1);
            const int ps = b - q;
            const int ib = g * LEN + q;
            float2 x0 = x[ib + ps];
            float2 x1 = x[ib + ps + Q];
            float2 x2 = x[ib + ps + 2*Q];
            float2 x3 = x[ib + ps + 3*Q];
            float2 w1 = tw[ps], w2 = tw[2*ps];
            if (SIGN > 0) { w1.y = -w1.y; w2.y = -w2.y; }
            float2 w3 = cmul(w1, w2);
            float2 e0 = make_float2(x0.x + x2.x, x0.y + x2.y);
            float2 e1 = make_float2(x0.x - x2.x, x0.y - x2.y);
            float2 o0 = make_float2(x1.x + x3.x, x1.y + x3.y);
            float2 d  = make_float2(x1.x - x3.x, x1.y - x3.y);
            float2 o1 = (SIGN > 0) ? make_float2(-d.y, d.x)   // +i*d
                                   : make_float2( d.y, -d.x); // -i*d
            const int ob = g * LEN + q + 4*ps;
            y[ob]       = make_float2(e0.x + o0.x, e0.y + o0.y);
            y[ob + s]   = cmul(make_float2(e1.x + o1.x, e1.y + o1.y), w1);
            y[ob + 2*s] = cmul(make_float2(e0.x - o0.x, e0.y - o0.y), w2);
            y[ob + 3*s] = cmul(make_float2(e1.x - o1.x, e1.y - o1.y), w3);
        }
        { float2* tp = x; x = y; y = tp; }
        s <<= 2;
    }
    __syncthreads();
    return x;
}

// ---------------------------------------------------------------------------
// k0: DPLR generator, one root per thread, grid=1024.
//     Omega via sincosf (float-pi inexactness keeps 1+Omega != 0 at Nyquist,
//     matching the float32 reference).  Writes matrix layout for k1.
// ---------------------------------------------------------------------------
#define TPB0 256
__global__ void k0_gen(const float* __restrict__ Lre, const float* __restrict__ Lim,
                       const float* __restrict__ Pre, const float* __restrict__ Pim,
                       const float* __restrict__ Bre, const float* __restrict__ Bim,
                       const float* __restrict__ Cri, const float* __restrict__ ls) {
    __shared__ float  sLre[64], sLim[64];
    __shared__ float2 sv0[64], sv1[64], sv2[64], sv3[64];
    const int t = threadIdx.x;
    if (t < 64) {
        float2 Pv = make_float2(Pre[t], Pim[t]);
        float2 Bv = make_float2(Bre[t], Bim[t]);
        float2 Cj = make_float2(Cri[2*t], -Cri[2*t+1]);   // conj(C)
        float2 Pj = make_float2(Pv.x, -Pv.y);             // conj(P) (Q = P)
        sLre[t] = Lre[t]; sLim[t] = Lim[t];
        sv0[t] = cmul(Cj, Bv); sv1[t] = cmul(Cj, Pv);
        sv2[t] = cmul(Pj, Bv); sv3[t] = cmul(Pj, Pv);
    }
    __syncthreads();

    const int j = blockIdx.x * TPB0 + t;
    const float step = expf(ls[0]);

    float ang = -PI2 * ((float)j / (float)L_SIZE);
    float sn, cs; sincosf(ang, &sn, &cs);          // Omega = cs + i*sn
    float2 onem = make_float2(1.f - cs, -sn);
    float2 onep = make_float2(1.f + cs,  sn);
    float invp = 1.f / (onep.x*onep.x + onep.y*onep.y);
    float2 cc = make_float2(2.f*onep.x*invp, -2.f*onep.y*invp);  // 2/(1+Om)
    float2 qv = cmul(onem, make_float2(onep.x, -onep.y));
    float sfac = (2.f / step) * invp;
    float gx = qv.x * sfac, gy = qv.y * sfac;

    float2 k00 = {0,0}, k01 = {0,0}, k10 = {0,0}, k11 = {0,0};
    #pragma unroll
    for (int n = 0; n < 64; ++n) {
        float dx = gx - sLre[n], dy = gy - sLim[n];
        float inv = 1.f / (dx*dx + dy*dy);
        float2 r = make_float2(dx*inv, -dy*inv);   // 1/(g - Lambda_n)
        k00 = cfma(r, sv0[n], k00);
        k01 = cfma(r, sv1[n], k01);
        k10 = cfma(r, sv2[n], k10);
        k11 = cfma(r, sv3[n], k11);
    }
    float2 den = make_float2(1.f + k11.x, k11.y);
    float invd = 1.f / (den.x*den.x + den.y*den.y);
    float2 num = cmul(k01, k10);
    float2 tq  = cmul(num, make_float2(den.x*invd, -den.y*invd));
    float2 at  = cmul(cc, make_float2(k00.x - tq.x, k00.y - tq.y));

    dA[((j & 511) << 9) | (j >> 9)] = at;   // row k1 = j mod 512, col m = j/512
}

// ---------------------------------------------------------------------------
// k1: IFFT_L row pass (len 512, 2 rows/block) + twiddle -> dB. grid=256
// ---------------------------------------------------------------------------
#define TPB1 256
__global__ void k1_rowfft() {
    __shared__ float2 s0[1024], s1[1024], tw[256];
    fill_tw<TPB1>(tw, 256, 512);
    const int row0 = blockIdx.x * 2;
    const float2* src = dA + row0 * 512;
    for (int i = threadIdx.x; i < 1024; i += TPB1) s0[i] = src[i];
    float2* r = stockham4<512, 9, 2, +1, TPB1>(s0, s1, tw);
    for (int i = threadIdx.x; i < 1024; i += TPB1) {
        int g = i >> 9, m = i & 511;
        int kk = row0 + g;
        int mm = (m * kk) & (L_SIZE - 1);
        dB[kk * 512 + m] = cmul(r[i], twiddle_c(mm, L_SIZE, 1.0f));
    }
}

// ---------------------------------------------------------------------------
// k2: IFFT_L column pass (len 512, 2 cols/block) -> dK. grid=256
// ---------------------------------------------------------------------------
#define TPB2 256
__global__ void k2_ifft_cols() {
    __shared__ float2 s0[1024], s1[1024], tw[256];
    fill_tw<TPB2>(tw, 256, 512);
    const int c0 = blockIdx.x * 2;
    for (int i = threadIdx.x; i < 1024; i += TPB2) {
        int g = i & 1, rr = i >> 1;
        s0[g * 512 + rr] = dB[rr * 512 + c0 + g];
    }
    float2* r = stockham4<512, 9, 2, +1, TPB2>(s0, s1, tw);
    const float invL = 1.0f / (float)L_SIZE;
    for (int i = threadIdx.x; i < 1024; i += TPB2) {
        int g = i & 1, p = i >> 1;
        dK[p * 512 + c0 + g] = r[g * 512 + p].x * invL;
    }
}

// ---------------------------------------------------------------------------
// k3: forward column FFTs (len 512) of z = u + i*K (zero-padded), + fwd
//     twiddle, write dA[k1*1024 + c]. 2 cols/block, grid=512
// ---------------------------------------------------------------------------
#define TPB3 256
__global__ void k3_fwd_cols(const float* __restrict__ u) {
    __shared__ float2 s0[1024], s1[1024], tw[256];
    fill_tw<TPB3>(tw, 256, 512);
    const int c0 = blockIdx.x * 2;
    for (int i = threadIdx.x; i < 1024; i += TPB3) {
        int g = i & 1, rr = i >> 1;
        float2 z = make_float2(0.f, 0.f);
        if (rr < 256) {
            int idx = rr * 1024 + c0 + g;
            z = make_float2(u[idx], dK[idx]);
        }
        s0[g * 512 + rr] = z;
    }
    float2* r = stockham4<512, 9, 2, -1, TPB3>(s0, s1, tw);
    for (int i = threadIdx.x; i < 1024; i += TPB3) {
        int g = i & 1, k1 = i >> 1;
        int c = c0 + g;
        int mm = (c * k1) & (N2L - 1);
        dA[k1 * 1024 + c] = cmul(r[g * 512 + k1], twiddle_c(mm, N2L, -1.0f));
    }
}

// ---------------------------------------------------------------------------
// k4 MEGA: paired rows (k1, 512-k1); block 0 takes self-paired rows {0, 256}.
//   fwd FFT1024 x2 -> Z; Hermitian split U,Kd + multiply -> Y;
//   inv FFT1024 x2 on Y; inv twiddle; write dB[k1*1024 + m]. grid=256
// ---------------------------------------------------------------------------
#define TPB4 512
__global__ void k4_mega() {
    __shared__ float2 s0[2048], s1[2048], tw[512];
    fill_tw<TPB4>(tw, 512, 1024);
    const int b = blockIdx.x;
    const int rowA = b;                       // b=0 -> row 0
    const int rowB = (b == 0) ? 256 : 512 - b;
    const int t = threadIdx.x;

    for (int i = t; i < 2048; i += TPB4) {
        int slot = i >> 10, m = i & 1023;
        int row = slot ? rowB : rowA;
        s0[i] = dA[row * 1024 + m];
    }
    float2* Z = stockham4<1024, 10, 2, -1, TPB4>(s0, s1, tw);
    float2* Y = (Z == s0) ? s1 : s0;

    // Pointwise: Y = U * Kd from Z and Hermitian partner.
    for (int i = t; i < 2048; i += TPB4) {
        int slot = i >> 10, k2 = i & 1023;
        float2 Zv = Z[i];
        float2 Zp;
        if (b == 0) {
            int pk2 = slot ? (1023 - k2) : ((1024 - k2) & 1023);
            Zp = Z[(slot << 10) + pk2];
        } else {
            Zp = Z[((1 - slot) << 10) + (1023 - k2)];
        }
        float2 U  = make_float2(0.5f * (Zv.x + Zp.x),  0.5f * (Zv.y - Zp.y));
        float2 Kd = make_float2(0.5f * (Zv.y + Zp.y), -0.5f * (Zv.x - Zp.x));
        Y[i] = cmul(U, Kd);
    }
    float2* r = stockham4<1024, 10, 2, +1, TPB4>(Y, Z, tw);
    for (int i = t; i < 2048; i += TPB4) {
        int slot = i >> 10, m = i & 1023;
        int kk = slot ? rowB : rowA;
        int mm = (m * kk) & (N2L - 1);
        dB[kk * 1024 + m] = cmul(r[i], twiddle_c(mm, N2L, 1.0f));
    }
}

// ---------------------------------------------------------------------------
// k5: inverse column FFTs (len 512, 2 cols/block); out[n] = Re/2L + D*u[n],
//     only first 256 rows (n < L). grid=512
// ---------------------------------------------------------------------------
#define TPB5 256
__global__ void k5_inv_cols(const float* __restrict__ u, const float* __restrict__ Dp,
                            float* __restrict__ out) {
    __shared__ float2 s0[1024], s1[1024], tw[256];
    fill_tw<TPB5>(tw, 256, 512);
    const int c0 = blockIdx.x * 2;
    for (int i = threadIdx.x; i < 1024; i += TPB5) {
        int g = i & 1, rr = i >> 1;
        s0[g * 512 + rr] = dB[rr * 1024 + c0 + g];
    }
    float2* r = stockham4<512, 9, 2, +1, TPB5>(s0, s1, tw);
    const float sc = 1.0f / (float)N2L;
    const float Dv = Dp[0];
    for (int i = threadIdx.x; i < 512; i += TPB5) {
        int g = i & 1, p = i >> 1;
        int n = p * 1024 + c0 + g;
        out[n] = fmaf(Dv, u[n], r[g * 512 + p].x * sc);
    }
}

// ---------------------------------------------------------------------------
extern "C" void kernel_launch(void* const* d_in, const int* in_sizes, int n_in,
                              void* d_out, int out_size) {
    (void)in_sizes; (void)n_in; (void)out_size;
    const float* u   = (const float*)d_in[0];
    const float* Lre = (const float*)d_in[1];
    const float* Lim = (const float*)d_in[2];
    const float* Pre = (const float*)d_in[3];
    const float* Pim = (const float*)d_in[4];
    const float* Bre = (const float*)d_in[5];
    const float* Bim = (const float*)d_in[6];
    const float* Cri = (const float*)d_in[7];
    const float* Dp  = (const float*)d_in[8];
    const float* ls  = (const float*)d_in[9];
    float* out = (float*)d_out;

    k0_gen       <<<1024, TPB0>>>(Lre, Lim, Pre, Pim, Bre, Bim, Cri, ls);
    k1_rowfft    <<<256,  TPB1>>>();
    k2_ifft_cols <<<256,  TPB2>>>();
    k3_fwd_cols  <<<512,  TPB3>>>(u);
    k4_mega      <<<256,  TPB4>>>();
    k5_inv_cols  <<<512,  TPB5>>>(u, Dp, out);
}

// round 5
// speedup vs baseline: 2.2244x; 1.3854x over previous
#include <cuda_runtime.h>

// S4 DPLR layer, round 5: radix-4 Stockham with 2 butterflies/thread/stage,
// coalesced generator writes, 4-column blocks.
//
// Pipeline (6 kernels):
//  k0: DPLR generator: atRoots[j] -> dA[k1*512 + m]  (j = k1 + 512 m),
//      warp-per-row tiling for coalesced stores
//  k1: row IFFT512 of dA + inter-pass twiddle -> dB     [IFFT_L pass 1]
//  k2: column IFFT512 of dB -> dK (= K, real, scaled 1/L)  [IFFT_L pass 2]
//  k3: column FFT512 of z = u + i*K (zero-padded), fwd twiddle -> dA
//  k4: MEGA: paired rows (k1, 512-k1): fwd FFT1024 x2, Hermitian split
//      U,Kd + multiply, inv FFT1024 x2, inv twiddle -> dB
//  k5: column IFFT512 of dB, emit out[n] = Re/2L + D*u[n]  (first L only)

#define L_SIZE   262144   // 2^18
#define N2L      524288   // 2^19
#define PI2      6.283185307179586f

__device__ float2 dA[N2L];    // 4 MB scratch
__device__ float2 dB[N2L];    // 4 MB scratch
__device__ float  dK[L_SIZE]; // 1 MB kernel K

static __device__ __forceinline__ float2 cmul(float2 a, float2 b) {
    return make_float2(a.x*b.x - a.y*b.y, a.x*b.y + a.y*b.x);
}
static __device__ __forceinline__ float2 cfma(float2 a, float2 b, float2 acc) {
    acc.x = fmaf(a.x, b.x, fmaf(-a.y, b.y, acc.x));
    acc.y = fmaf(a.x, b.y, fmaf( a.y, b.x, acc.y));
    return acc;
}

// Table: tw[k] = exp(-2*pi*i*k/len), k in [0, len/2).  (forward sign baked)
template<int NT>
static __device__ __forceinline__ void fill_tw(float2* tw, int half, int len) {
    for (int k = threadIdx.x; k < half; k += NT) {
        float s, c;
        sincospif(-2.0f * (float)k / (float)len, &s, &c);
        tw[k] = make_float2(c, s);
    }
}

// exp(sgn * 2*pi*i * mm / n), mm in [0, n). Centered arg -> __sincosf safe.
static __device__ __forceinline__ float2 twiddle_c(int mm, int n, float sgn) {
    int tt = mm - ((mm >= (n >> 1)) ? n : 0);
    float ang = sgn * (PI2 / (float)n) * (float)tt;
    float s, c; __sincosf(ang, &s, &c);
    return make_float2(c, s);
}

// Radix-4 Stockham (radix-2 first stage when LOG odd). NFFT batched length-LEN
// FFTs in smem; batch g at x[g*LEN + i]. Natural-order I/O. Table tw is
// forward-signed; SIGN=-1 forward, SIGN=+1 inverse (conjugates table).
template<int LEN, int LOG, int NFFT, int SIGN, int NT>
static __device__ __forceinline__ float2* stockham4(float2* x, float2* y, const float2* tw) {
    constexpr int H = LEN >> 1, Q = LEN >> 2;
    int s = 1;
    if (LOG & 1) {
        __syncthreads();
        #pragma unroll
        for (int u0 = 0; u0 < NFFT * H / NT; ++u0) {
            const int bi = u0 * NT + threadIdx.x;
            const int g = bi >> (LOG - 1);
            const int p = bi & (H - 1);
            const int base = g * LEN;
            float2 a = x[base + p], c = x[base + p + H];
            float2 w = tw[p]; if (SIGN > 0) w.y = -w.y;
            y[base + 2*p]     = make_float2(a.x + c.x, a.y + c.y);
            y[base + 2*p + 1] = cmul(make_float2(a.x - c.x, a.y - c.y), w);
        }
        { float2* tp = x; x = y; y = tp; }
        s = 2;
    }
    while (s < LEN) {
        __syncthreads();
        #pragma unroll
        for (int u0 = 0; u0 < NFFT * Q / NT; ++u0) {
            const int bi = u0 * NT + threadIdx.x;
            const int g  = bi >> (LOG - 2);
            const int b  = bi & (Q - 1);
            const int q  = b & (s - 1);
            const int ps = b - q;
            const int ib = g * LEN + q;
            float2 x0 = x[ib + ps];
            float2 x1 = x[ib + ps + Q];
            float2 x2 = x[ib + ps + 2*Q];
            float2 x3 = x[ib + ps + 3*Q];
            float2 w1 = tw[ps], w2 = tw[2*ps];
            if (SIGN > 0) { w1.y = -w1.y; w2.y = -w2.y; }
            float2 w3 = cmul(w1, w2);
            float2 e0 = make_float2(x0.x + x2.x, x0.y + x2.y);
            float2 e1 = make_float2(x0.x - x2.x, x0.y - x2.y);
            float2 o0 = make_float2(x1.x + x3.x, x1.y + x3.y);
            float2 d  = make_float2(x1.x - x3.x, x1.y - x3.y);
            float2 o1 = (SIGN > 0) ? make_float2(-d.y, d.x)   // +i*d
                                   : make_float2( d.y, -d.x); // -i*d
            const int ob = g * LEN + q + 4*ps;
            y[ob]       = make_float2(e0.x + o0.x, e0.y + o0.y);
            y[ob + s]   = cmul(make_float2(e1.x + o1.x, e1.y + o1.y), w1);
            y[ob + 2*s] = cmul(make_float2(e0.x - o0.x, e0.y - o0.y), w2);
            y[ob + 3*s] = cmul(make_float2(e1.x - o1.x, e1.y - o1.y), w3);
        }
        { float2* tp = x; x = y; y = tp; }
        s <<= 2;
    }
    __syncthreads();
    return x;
}

// ---------------------------------------------------------------------------
// k0: DPLR generator, grid=1024 x 256. Tile: 8 rows (k1, one per warp) x
//     32 cols (m, one per lane) -> stores are 256B contiguous per warp.
//     Omega via sincosf (keeps 1+Omega != 0 at Nyquist like the f32 ref).
// ---------------------------------------------------------------------------
#define TPB0 256
__global__ void k0_gen(const float* __restrict__ Lre, const float* __restrict__ Lim,
                       const float* __restrict__ Pre, const float* __restrict__ Pim,
                       const float* __restrict__ Bre, const float* __restrict__ Bim,
                       const float* __restrict__ Cri, const float* __restrict__ ls) {
    __shared__ float  sLre[64], sLim[64];
    __shared__ float2 sv0[64], sv1[64], sv2[64], sv3[64];
    const int t = threadIdx.x;
    if (t < 64) {
        float2 Pv = make_float2(Pre[t], Pim[t]);
        float2 Bv = make_float2(Bre[t], Bim[t]);
        float2 Cj = make_float2(Cri[2*t], -Cri[2*t+1]);   // conj(C)
        float2 Pj = make_float2(Pv.x, -Pv.y);             // conj(P) (Q = P)
        sLre[t] = Lre[t]; sLim[t] = Lim[t];
        sv0[t] = cmul(Cj, Bv); sv1[t] = cmul(Cj, Pv);
        sv2[t] = cmul(Pj, Bv); sv3[t] = cmul(Pj, Pv);
    }
    __syncthreads();

    const int b = blockIdx.x;
    const int k1 = (b & 63) * 8 + (t >> 5);
    const int m  = (b >> 6) * 32 + (t & 31);
    const int j  = k1 + (m << 9);
    const float step = expf(ls[0]);

    float ang = -PI2 * ((float)j / (float)L_SIZE);
    float sn, cs; sincosf(ang, &sn, &cs);          // Omega = cs + i*sn
    float2 onem = make_float2(1.f - cs, -sn);
    float2 onep = make_float2(1.f + cs,  sn);
    float invp = 1.f / (onep.x*onep.x + onep.y*onep.y);
    float2 cc = make_float2(2.f*onep.x*invp, -2.f*onep.y*invp);  // 2/(1+Om)
    float2 qv = cmul(onem, make_float2(onep.x, -onep.y));
    float sfac = (2.f / step) * invp;
    float gx = qv.x * sfac, gy = qv.y * sfac;

    float2 k00 = {0,0}, k01 = {0,0}, k10 = {0,0}, k11 = {0,0};
    #pragma unroll
    for (int n = 0; n < 64; ++n) {
        float dx = gx - sLre[n], dy = gy - sLim[n];
        float inv = 1.f / (dx*dx + dy*dy);
        float2 r = make_float2(dx*inv, -dy*inv);   // 1/(g - Lambda_n)
        k00 = cfma(r, sv0[n], k00);
        k01 = cfma(r, sv1[n], k01);
        k10 = cfma(r, sv2[n], k10);
        k11 = cfma(r, sv3[n], k11);
    }
    float2 den = make_float2(1.f + k11.x, k11.y);
    float invd = 1.f / (den.x*den.x + den.y*den.y);
    float2 num = cmul(k01, k10);
    float2 tq  = cmul(num, make_float2(den.x*invd, -den.y*invd));
    float2 at  = cmul(cc, make_float2(k00.x - tq.x, k00.y - tq.y));

    dA[k1 * 512 + m] = at;
}

// ---------------------------------------------------------------------------
// k1: IFFT_L row pass (len 512, 4 rows/block) + twiddle -> dB. grid=128
// ---------------------------------------------------------------------------
#define TPB1 256
__global__ void k1_rowfft() {
    __shared__ float2 s0[2048], s1[2048], tw[256];
    fill_tw<TPB1>(tw, 256, 512);
    const int row0 = blockIdx.x * 4;
    const float2* src = dA + row0 * 512;
    for (int i = threadIdx.x; i < 2048; i += TPB1) s0[i] = src[i];
    float2* r = stockham4<512, 9, 4, +1, TPB1>(s0, s1, tw);
    for (int i = threadIdx.x; i < 2048; i += TPB1) {
        int g = i >> 9, m = i & 511;
        int kk = row0 + g;
        int mm = (m * kk) & (L_SIZE - 1);
        dB[kk * 512 + m] = cmul(r[i], twiddle_c(mm, L_SIZE, 1.0f));
    }
}

// ---------------------------------------------------------------------------
// k2: IFFT_L column pass (len 512, 4 cols/block) -> dK. grid=128
// ---------------------------------------------------------------------------
#define TPB2 256
__global__ void k2_ifft_cols() {
    __shared__ float2 s0[2048], s1[2048], tw[256];
    fill_tw<TPB2>(tw, 256, 512);
    const int c0 = blockIdx.x * 4;
    for (int i = threadIdx.x; i < 2048; i += TPB2) {
        int g = i & 3, rr = i >> 2;
        s0[g * 512 + rr] = dB[rr * 512 + c0 + g];
    }
    float2* r = stockham4<512, 9, 4, +1, TPB2>(s0, s1, tw);
    const float invL = 1.0f / (float)L_SIZE;
    for (int i = threadIdx.x; i < 2048; i += TPB2) {
        int g = i & 3, p = i >> 2;
        dK[p * 512 + c0 + g] = r[g * 512 + p].x * invL;
    }
}

// ---------------------------------------------------------------------------
// k3: forward column FFTs (len 512, 4 cols/block) of z = u + i*K
//     (zero-padded), + fwd twiddle, write dA[k1*1024 + c]. grid=256
// ---------------------------------------------------------------------------
#define TPB3 256
__global__ void k3_fwd_cols(const float* __restrict__ u) {
    __shared__ float2 s0[2048], s1[2048], tw[256];
    fill_tw<TPB3>(tw, 256, 512);
    const int c0 = blockIdx.x * 4;
    for (int i = threadIdx.x; i < 2048; i += TPB3) {
        int g = i & 3, rr = i >> 2;
        float2 z = make_float2(0.f, 0.f);
        if (rr < 256) {
            int idx = rr * 1024 + c0 + g;
            z = make_float2(u[idx], dK[idx]);
        }
        s0[g * 512 + rr] = z;
    }
    float2* r = stockham4<512, 9, 4, -1, TPB3>(s0, s1, tw);
    for (int i = threadIdx.x; i < 2048; i += TPB3) {
        int g = i & 3, k1 = i >> 2;
        int c = c0 + g;
        int mm = (c * k1) & (N2L - 1);
        dA[k1 * 1024 + c] = cmul(r[g * 512 + k1], twiddle_c(mm, N2L, -1.0f));
    }
}

// ---------------------------------------------------------------------------
// k4 MEGA: paired rows (k1, 512-k1); block 0 takes self-paired rows {0, 256}.
//   fwd FFT1024 x2 -> Z; Hermitian split U,Kd + multiply -> Y;
//   inv FFT1024 x2 on Y; inv twiddle; write dB[k1*1024 + m].
//   TPB=256 -> 2 radix-4 butterflies per thread per stage. grid=256
// ---------------------------------------------------------------------------
#define TPB4 256
__global__ void k4_mega() {
    __shared__ float2 s0[2048], s1[2048], tw[512];
    fill_tw<TPB4>(tw, 512, 1024);
    const int b = blockIdx.x;
    const int rowA = b;                       // b=0 -> row 0
    const int rowB = (b == 0) ? 256 : 512 - b;
    const int t = threadIdx.x;

    for (int i = t; i < 2048; i += TPB4) {
        int slot = i >> 10, m = i & 1023;
        int row = slot ? rowB : rowA;
        s0[i] = dA[row * 1024 + m];
    }
    float2* Z = stockham4<1024, 10, 2, -1, TPB4>(s0, s1, tw);
    float2* Y = (Z == s0) ? s1 : s0;

    // Pointwise: Y = U * Kd from Z and Hermitian partner.
    for (int i = t; i < 2048; i += TPB4) {
        int slot = i >> 10, k2 = i & 1023;
        float2 Zv = Z[i];
        float2 Zp;
        if (b == 0) {
            int pk2 = slot ? (1023 - k2) : ((1024 - k2) & 1023);
            Zp = Z[(slot << 10) + pk2];
        } else {
            Zp = Z[((1 - slot) << 10) + (1023 - k2)];
        }
        float2 U  = make_float2(0.5f * (Zv.x + Zp.x),  0.5f * (Zv.y - Zp.y));
        float2 Kd = make_float2(0.5f * (Zv.y + Zp.y), -0.5f * (Zv.x - Zp.x));
        Y[i] = cmul(U, Kd);
    }
    float2* r = stockham4<1024, 10, 2, +1, TPB4>(Y, Z, tw);
    for (int i = t; i < 2048; i += TPB4) {
        int slot = i >> 10, m = i & 1023;
        int kk = slot ? rowB : rowA;
        int mm = (m * kk) & (N2L - 1);
        dB[kk * 1024 + m] = cmul(r[i], twiddle_c(mm, N2L, 1.0f));
    }
}

// ---------------------------------------------------------------------------
// k5: inverse column FFTs (len 512, 4 cols/block); out[n] = Re/2L + D*u[n],
//     only first 256 rows (n < L). grid=256
// ---------------------------------------------------------------------------
#define TPB5 256
__global__ void k5_inv_cols(const float* __restrict__ u, const float* __restrict__ Dp,
                            float* __restrict__ out) {
    __shared__ float2 s0[2048], s1[2048], tw[256];
    fill_tw<TPB5>(tw, 256, 512);
    const int c0 = blockIdx.x * 4;
    for (int i = threadIdx.x; i < 2048; i += TPB5) {
        int g = i & 3, rr = i >> 2;
        s0[g * 512 + rr] = dB[rr * 1024 + c0 + g];
    }
    float2* r = stockham4<512, 9, 4, +1, TPB5>(s0, s1, tw);
    const float sc = 1.0f / (float)N2L;
    const float Dv = Dp[0];
    for (int i = threadIdx.x; i < 1024; i += TPB5) {
        int g = i & 3, p = i >> 2;
        int n = p * 1024 + c0 + g;
        out[n] = fmaf(Dv, u[n], r[g * 512 + p].x * sc);
    }
}

// ---------------------------------------------------------------------------
extern "C" void kernel_launch(void* const* d_in, const int* in_sizes, int n_in,
                              void* d_out, int out_size) {
    (void)in_sizes; (void)n_in; (void)out_size;
    const float* u   = (const float*)d_in[0];
    const float* Lre = (const float*)d_in[1];
    const float* Lim = (const float*)d_in[2];
    const float* Pre = (const float*)d_in[3];
    const float* Pim = (const float*)d_in[4];
    const float* Bre = (const float*)d_in[5];
    const float* Bim = (const float*)d_in[6];
    const float* Cri = (const float*)d_in[7];
    const float* Dp  = (const float*)d_in[8];
    const float* ls  = (const float*)d_in[9];
    float* out = (float*)d_out;

    k0_gen       <<<1024, TPB0>>>(Lre, Lim, Pre, Pim, Bre, Bim, Cri, ls);
    k1_rowfft    <<<128,  TPB1>>>();
    k2_ifft_cols <<<128,  TPB2>>>();
    k3_fwd_cols  <<<256,  TPB3>>>(u);
    k4_mega      <<<256,  TPB4>>>();
    k5_inv_cols  <<<256,  TPB5>>>(u, Dp, out);
}

// round 7
// speedup vs baseline: 2.2800x; 1.0250x over previous
#include <cuda_runtime.h>

// S4 DPLR layer, round 7: register-resident radix-8 FFTs (3 smem exchanges
// per 512-pt FFT instead of 5 barrier stages), 1024-pt via radix-2 split.
// (R6 NaN fix: k0 reverted to per-element reciprocals — batching 4 |.|^2
//  magnitudes overflowed float range near the Nyquist root.)
//
// Pipeline (6 kernels):
//  k0: DPLR generator -> dA[k1*512 + m]  (j = k1 + 512 m)
//  k1: row IFFT512 of dA + four-step twiddle -> dB      [IFFT_L pass 1]
//  k2: column IFFT512 of dB -> dK (real, scaled 1/L)    [IFFT_L pass 2]
//  k3: column FFT512 of z = u + i*K (zero-padded), fwd twiddle -> dA
//  k4: MEGA: paired rows (k1, 512-k1): fwd FFT1024 x2 (radix-2 split into
//      2x FFT512), Hermitian split U,Kd + multiply, inv FFT1024 x2,
//      inv twiddle -> dB
//  k5: column IFFT512 of dB, out[n] = Re/2L + D*u[n]  (first L only)

#define L_SIZE   262144   // 2^18
#define N2L      524288   // 2^19
#define PI2      6.283185307179586f
#define RT2      0.70710678118654752f

__device__ float2 dA[N2L];    // 4 MB scratch
__device__ float2 dB[N2L];    // 4 MB scratch
__device__ float  dK[L_SIZE]; // 1 MB kernel K

static __device__ __forceinline__ float2 cmul(float2 a, float2 b) {
    return make_float2(a.x*b.x - a.y*b.y, a.x*b.y + a.y*b.x);
}
static __device__ __forceinline__ float2 cadd(float2 a, float2 b) {
    return make_float2(a.x + b.x, a.y + b.y);
}
static __device__ __forceinline__ float2 csub(float2 a, float2 b) {
    return make_float2(a.x - b.x, a.y - b.y);
}
static __device__ __forceinline__ float2 cfma(float2 a, float2 b, float2 acc) {
    acc.x = fmaf(a.x, b.x, fmaf(-a.y, b.y, acc.x));
    acc.y = fmaf(a.x, b.y, fmaf( a.y, b.x, acc.y));
    return acc;
}

// tw[k] = exp(-2*pi*i*k/len), k in [0, cnt)
template<int NT>
static __device__ __forceinline__ void fill_tw(float2* tw, int cnt, int len) {
    for (int k = threadIdx.x; k < cnt; k += NT) {
        float s, c;
        sincospif(-2.0f * (float)k / (float)len, &s, &c);
        tw[k] = make_float2(c, s);
    }
}

// exp(sgn * 2*pi*i * mm / n), mm in [0, n). Centered arg -> __sincosf safe.
static __device__ __forceinline__ float2 twiddle_c(int mm, int n, float sgn) {
    int tt = mm - ((mm >= (n >> 1)) ? n : 0);
    float ang = sgn * (PI2 / (float)n) * (float)tt;
    float s, c; __sincosf(ang, &s, &c);
    return make_float2(c, s);
}

// Table lookup with sign: forward table exp(-...), inverse conjugates.
template<int SIGN>
static __device__ __forceinline__ float2 twl(const float2* tw, int idx) {
    float2 w = tw[idx];
    if (SIGN > 0) w.y = -w.y;
    return w;
}

// multiply by (-i) forward / (+i) inverse
template<int SIGN>
static __device__ __forceinline__ float2 mulpmi(float2 a) {
    return (SIGN < 0) ? make_float2(a.y, -a.x) : make_float2(-a.y, a.x);
}
// multiply by W8^1 (fwd (1-i)/sqrt2, inv (1+i)/sqrt2)
template<int SIGN>
static __device__ __forceinline__ float2 mulw81(float2 a) {
    return (SIGN < 0) ? make_float2(RT2*(a.x + a.y), RT2*(a.y - a.x))
                      : make_float2(RT2*(a.x - a.y), RT2*(a.x + a.y));
}
// multiply by W8^3 (fwd (-1-i)/sqrt2, inv (-1+i)/sqrt2)
template<int SIGN>
static __device__ __forceinline__ float2 mulw83(float2 a) {
    return (SIGN < 0) ? make_float2(RT2*(a.y - a.x), RT2*(-a.x - a.y))
                      : make_float2(RT2*(-a.x - a.y), RT2*(a.x - a.y));
}

// 8-point FFT in registers, natural order in/out. SIGN=-1 fwd, +1 inv.
template<int SIGN>
static __device__ __forceinline__ void fft8(float2 v[8]) {
    float2 t0 = cadd(v[0], v[4]), t1 = csub(v[0], v[4]);
    float2 t2 = cadd(v[2], v[6]), t3 = mulpmi<SIGN>(csub(v[2], v[6]));
    float2 E0 = cadd(t0, t2), E1 = cadd(t1, t3);
    float2 E2 = csub(t0, t2), E3 = csub(t1, t3);
    float2 u0 = cadd(v[1], v[5]), u1 = csub(v[1], v[5]);
    float2 u2 = cadd(v[3], v[7]), u3 = mulpmi<SIGN>(csub(v[3], v[7]));
    float2 O0 = cadd(u0, u2), O1 = cadd(u1, u3);
    float2 O2 = csub(u0, u2), O3 = csub(u1, u3);
    O1 = mulw81<SIGN>(O1);
    O2 = mulpmi<SIGN>(O2);
    O3 = mulw83<SIGN>(O3);
    v[0] = cadd(E0, O0); v[4] = csub(E0, O0);
    v[1] = cadd(E1, O1); v[5] = csub(E1, O1);
    v[2] = cadd(E2, O2); v[6] = csub(E2, O2);
    v[3] = cadd(E3, O3); v[7] = csub(E3, O3);
}

// 512-pt FFT, 64 threads per FFT (l in [0,64)), 8 points/thread.
// Natural-order input in `in` chunk [base, base+512); natural-order output
// in `out` chunk. `in` is clobbered. tw = 512-entry forward table.
// Caller must __syncthreads() after filling `in`. Ends with __syncthreads().
// Decomposition n = n2*64 + n1*8 + n0 -> k = k0 + 8*k1 + 64*k2.
template<int SIGN>
static __device__ __forceinline__ void fft512_reg(
    float2* in, float2* out, int base, int l, const float2* tw)
{
    float2 v[8];
    #pragma unroll
    for (int e = 0; e < 8; ++e) v[e] = in[base + l + 64*e];
    fft8<SIGN>(v);                       // over n2 -> k0
    {
        const int n1 = l >> 3;
        #pragma unroll
        for (int k0 = 1; k0 < 8; ++k0)   // W64^{n1 k0} = tw512[8 n1 k0]
            v[k0] = cmul(v[k0], twl<SIGN>(tw, 8 * n1 * k0));
        #pragma unroll
        for (int k0 = 0; k0 < 8; ++k0) out[base + k0*64 + l] = v[k0];
    }
    __syncthreads();
    const int k0 = l >> 3, n0 = l & 7;
    #pragma unroll
    for (int n1 = 0; n1 < 8; ++n1) v[n1] = out[base + k0*64 + n1*8 + n0];
    fft8<SIGN>(v);                       // over n1 -> k1
    #pragma unroll
    for (int k1 = 0; k1 < 8; ++k1)       // W512^{n0 (k0 + 8 k1)}
        v[k1] = cmul(v[k1], twl<SIGN>(tw, n0 * (k0 + 8*k1)));
    #pragma unroll
    for (int k1 = 0; k1 < 8; ++k1) in[base + k0*64 + n0*8 + k1] = v[k1];
    __syncthreads();
    #pragma unroll
    for (int n0r = 0; n0r < 8; ++n0r) v[n0r] = in[base + k0*64 + n0r*8 + (l & 7)];
    fft8<SIGN>(v);                       // over n0 -> k2  (here l&7 plays k1)
    #pragma unroll
    for (int k2 = 0; k2 < 8; ++k2) out[base + k0 + 8*(l & 7) + 64*k2] = v[k2];
    __syncthreads();
}

// ---------------------------------------------------------------------------
// k0: DPLR generator, grid=1024 x 256. Tile: 8 rows (k1, per warp) x 32 cols
//     (m, per lane) -> coalesced 256B stores. Omega via sincosf (keeps
//     1+Omega != 0 at Nyquist like the f32 reference). Per-element recips
//     (values reach ~2e21; batching products overflows float).
// ---------------------------------------------------------------------------
#define TPB0 256
__global__ void k0_gen(const float* __restrict__ Lre, const float* __restrict__ Lim,
                       const float* __restrict__ Pre, const float* __restrict__ Pim,
                       const float* __restrict__ Bre, const float* __restrict__ Bim,
                       const float* __restrict__ Cri, const float* __restrict__ ls) {
    __shared__ float  sLre[64], sLim[64];
    __shared__ float2 sv0[64], sv1[64], sv2[64], sv3[64];
    const int t = threadIdx.x;
    if (t < 64) {
        float2 Pv = make_float2(Pre[t], Pim[t]);
        float2 Bv = make_float2(Bre[t], Bim[t]);
        float2 Cj = make_float2(Cri[2*t], -Cri[2*t+1]);   // conj(C)
        float2 Pj = make_float2(Pv.x, -Pv.y);             // conj(P) (Q = P)
        sLre[t] = Lre[t]; sLim[t] = Lim[t];
        sv0[t] = cmul(Cj, Bv); sv1[t] = cmul(Cj, Pv);
        sv2[t] = cmul(Pj, Bv); sv3[t] = cmul(Pj, Pv);
    }
    __syncthreads();

    const int b = blockIdx.x;
    const int k1 = (b & 63) * 8 + (t >> 5);
    const int m  = (b >> 6) * 32 + (t & 31);
    const int j  = k1 + (m << 9);
    const float step = expf(ls[0]);

    float ang = -PI2 * ((float)j / (float)L_SIZE);
    float sn, cs; sincosf(ang, &sn, &cs);          // Omega = cs + i*sn
    float2 onem = make_float2(1.f - cs, -sn);
    float2 onep = make_float2(1.f + cs,  sn);
    float invp = 1.f / (onep.x*onep.x + onep.y*onep.y);
    float2 cc = make_float2(2.f*onep.x*invp, -2.f*onep.y*invp);  // 2/(1+Om)
    float2 qv = cmul(onem, make_float2(onep.x, -onep.y));
    float sfac = (2.f / step) * invp;
    float gx = qv.x * sfac, gy = qv.y * sfac;

    float2 k00 = {0,0}, k01 = {0,0}, k10 = {0,0}, k11 = {0,0};
    #pragma unroll
    for (int n = 0; n < 64; ++n) {
        float dx = gx - sLre[n], dy = gy - sLim[n];
        float inv = 1.f / (dx*dx + dy*dy);
        float2 r = make_float2(dx*inv, -dy*inv);   // 1/(g - Lambda_n)
        k00 = cfma(r, sv0[n], k00);
        k01 = cfma(r, sv1[n], k01);
        k10 = cfma(r, sv2[n], k10);
        k11 = cfma(r, sv3[n], k11);
    }
    float2 den = make_float2(1.f + k11.x, k11.y);
    float invd = 1.f / (den.x*den.x + den.y*den.y);
    float2 num = cmul(k01, k10);
    float2 tq2 = cmul(num, make_float2(den.x*invd, -den.y*invd));
    float2 at  = cmul(cc, make_float2(k00.x - tq2.x, k00.y - tq2.y));

    dA[k1 * 512 + m] = at;
}

// ---------------------------------------------------------------------------
// k1: IFFT_L row pass (4 rows/block, radix-8) + twiddle -> dB. grid=128
// ---------------------------------------------------------------------------
#define TPB1 256
__global__ void k1_rowfft() {
    __shared__ float2 sa[2048], sb[2048], tw[512];
    fill_tw<TPB1>(tw, 512, 512);
    const int row0 = blockIdx.x * 4;
    const float2* src = dA + row0 * 512;
    for (int i = threadIdx.x; i < 2048; i += TPB1) sa[i] = src[i];
    __syncthreads();
    fft512_reg<+1>(sa, sb, (threadIdx.x >> 6) * 512, threadIdx.x & 63, tw);
    for (int i = threadIdx.x; i < 2048; i += TPB1) {
        int g = i >> 9, m = i & 511;
        int kk = row0 + g;
        int mm = (m * kk) & (L_SIZE - 1);
        dB[kk * 512 + m] = cmul(sb[i], twiddle_c(mm, L_SIZE, 1.0f));
    }
}

// ---------------------------------------------------------------------------
// k2: IFFT_L column pass (4 cols/block, radix-8) -> dK. grid=128
// ---------------------------------------------------------------------------
#define TPB2 256
__global__ void k2_ifft_cols() {
    __shared__ float2 sa[2048], sb[2048], tw[512];
    fill_tw<TPB2>(tw, 512, 512);
    const int c0 = blockIdx.x * 4;
    for (int i = threadIdx.x; i < 2048; i += TPB2) {
        int g = i & 3, rr = i >> 2;
        sa[g * 512 + rr] = dB[rr * 512 + c0 + g];
    }
    __syncthreads();
    fft512_reg<+1>(sa, sb, (threadIdx.x >> 6) * 512, threadIdx.x & 63, tw);
    const float invL = 1.0f / (float)L_SIZE;
    for (int i = threadIdx.x; i < 2048; i += TPB2) {
        int g = i & 3, p = i >> 2;
        dK[p * 512 + c0 + g] = sb[g * 512 + p].x * invL;
    }
}

// ---------------------------------------------------------------------------
// k3: forward column FFTs of z = u + i*K (zero-padded), 4 cols/block,
//     + fwd four-step twiddle, write dA[k1*1024 + c]. grid=256
// ---------------------------------------------------------------------------
#define TPB3 256
__global__ void k3_fwd_cols(const float* __restrict__ u) {
    __shared__ float2 sa[2048], sb[2048], tw[512];
    fill_tw<TPB3>(tw, 512, 512);
    const int c0 = blockIdx.x * 4;
    for (int i = threadIdx.x; i < 2048; i += TPB3) {
        int g = i & 3, rr = i >> 2;
        float2 z = make_float2(0.f, 0.f);
        if (rr < 256) {
            int idx = rr * 1024 + c0 + g;
            z = make_float2(u[idx], dK[idx]);
        }
        sa[g * 512 + rr] = z;
    }
    __syncthreads();
    fft512_reg<-1>(sa, sb, (threadIdx.x >> 6) * 512, threadIdx.x & 63, tw);
    for (int i = threadIdx.x; i < 2048; i += TPB3) {
        int g = i & 3, k1 = i >> 2;
        int c = c0 + g;
        int mm = (c * k1) & (N2L - 1);
        dA[k1 * 1024 + c] = cmul(sb[g * 512 + k1], twiddle_c(mm, N2L, -1.0f));
    }
}

// ---------------------------------------------------------------------------
// k4 MEGA: paired rows (k1, 512-k1); block 0 takes self-paired rows {0, 256}.
//   FFT1024 done as radix-2 split: X[2r] = FFT512(a+b), X[2r+1] =
//   FFT512((a-b)*W1024^m). Z stored interleaved [slot*1024 + (k&1)*512 +
//   (k>>1)]. Hermitian split + multiply, inverse = 2x IFFT512 + combine
//   y[m] = E' + V^m O', y[m+512] = E' - V^m O'. grid=256, TPB=256.
// ---------------------------------------------------------------------------
#define TPB4 256
__global__ void k4_mega() {
    __shared__ float2 sa[2048], sb[2048], tw[512], twh[512];
    fill_tw<TPB4>(tw, 512, 512);
    fill_tw<TPB4>(twh, 512, 1024);      // W1024^m, m in [0,512)
    const int b = blockIdx.x;
    const int rowA = b;                       // b=0 -> row 0
    const int rowB = (b == 0) ? 256 : 512 - b;
    const int t = threadIdx.x;

    for (int i = t; i < 2048; i += TPB4) {
        int slot = i >> 10, m = i & 1023;
        int row = slot ? rowB : rowA;
        sa[i] = dA[row * 1024 + m];
    }
    __syncthreads();
    // forward radix-2 pre-stage into sb (even half 0, odd half 1 per slot)
    for (int i = t; i < 1024; i += TPB4) {
        int slot = i >> 9, m = i & 511;
        float2 a = sa[slot * 1024 + m];
        float2 c = sa[slot * 1024 + m + 512];
        sb[slot * 1024 + m]       = cadd(a, c);
        sb[slot * 1024 + 512 + m] = cmul(csub(a, c), twh[m]);
    }
    __syncthreads();
    // 4 concurrent forward FFT512s (slot x half)
    fft512_reg<-1>(sb, sa, (t >> 6) * 512, t & 63, tw);
    // sa: Z[k] at [slot*1024 + (k&1)*512 + (k>>1)], natural k per row.
    // Pointwise Y = U*Kd via Hermitian partner, into sb (same layout).
    for (int i = t; i < 2048; i += TPB4) {
        int slot = i >> 10, half = (i >> 9) & 1, r = i & 511;
        int k = 2 * r + half;
        int pslot, pk;
        if (b == 0) {
            pslot = slot;
            pk = slot ? (1023 - k) : ((1024 - k) & 1023);
        } else {
            pslot = 1 - slot;
            pk = 1023 - k;
        }
        float2 Zv = sa[i];
        float2 Zp = sa[pslot * 1024 + (pk & 1) * 512 + (pk >> 1)];
        float2 U  = make_float2(0.5f * (Zv.x + Zp.x),  0.5f * (Zv.y - Zp.y));
        float2 Kd = make_float2(0.5f * (Zv.y + Zp.y), -0.5f * (Zv.x - Zp.x));
        sb[i] = cmul(U, Kd);
    }
    __syncthreads();
    // 4 concurrent inverse FFT512s: E' (half0), O' (half1) per slot -> sa
    fft512_reg<+1>(sb, sa, (t >> 6) * 512, t & 63, tw);
    // combine + inverse four-step twiddle + store
    for (int i = t; i < 1024; i += TPB4) {
        int slot = i >> 9, m = i & 511;
        float2 E = sa[slot * 1024 + m];
        float2 O = sa[slot * 1024 + 512 + m];
        float2 Vm = make_float2(twh[m].x, -twh[m].y);   // conj -> +2pi/1024
        float2 w  = cmul(Vm, O);
        float2 y0 = cadd(E, w);
        float2 y1 = csub(E, w);
        int kk = slot ? rowB : rowA;
        int mm0 = (m * kk) & (N2L - 1);
        int mm1 = ((m + 512) * kk) & (N2L - 1);
        dB[kk * 1024 + m]       = cmul(y0, twiddle_c(mm0, N2L, 1.0f));
        dB[kk * 1024 + m + 512] = cmul(y1, twiddle_c(mm1, N2L, 1.0f));
    }
}

// ---------------------------------------------------------------------------
// k5: inverse column FFTs (4 cols/block); out[n] = Re/2L + D*u[n],
//     only first 256 rows (n < L). grid=256
// ---------------------------------------------------------------------------
#define TPB5 256
__global__ void k5_inv_cols(const float* __restrict__ u, const float* __restrict__ Dp,
                            float* __restrict__ out) {
    __shared__ float2 sa[2048], sb[2048], tw[512];
    fill_tw<TPB5>(tw, 512, 512);
    const int c0 = blockIdx.x * 4;
    for (int i = threadIdx.x; i < 2048; i += TPB5) {
        int g = i & 3, rr = i >> 2;
        sa[g * 512 + rr] = dB[rr * 1024 + c0 + g];
    }
    __syncthreads();
    fft512_reg<+1>(sa, sb, (threadIdx.x >> 6) * 512, threadIdx.x & 63, tw);
    const float sc = 1.0f / (float)N2L;
    const float Dv = Dp[0];
    for (int i = threadIdx.x; i < 1024; i += TPB5) {
        int g = i & 3, p = i >> 2;
        int n = p * 1024 + c0 + g;
        out[n] = fmaf(Dv, u[n], sb[g * 512 + p].x * sc);
    }
}

// ---------------------------------------------------------------------------
extern "C" void kernel_launch(void* const* d_in, const int* in_sizes, int n_in,
                              void* d_out, int out_size) {
    (void)in_sizes; (void)n_in; (void)out_size;
    const float* u   = (const float*)d_in[0];
    const float* Lre = (const float*)d_in[1];
    const float* Lim = (const float*)d_in[2];
    const float* Pre = (const float*)d_in[3];
    const float* Pim = (const float*)d_in[4];
    const float* Bre = (const float*)d_in[5];
    const float* Bim = (const float*)d_in[6];
    const float* Cri = (const float*)d_in[7];
    const float* Dp  = (const float*)d_in[8];
    const float* ls  = (const float*)d_in[9];
    float* out = (float*)d_out;

    k0_gen       <<<1024, TPB0>>>(Lre, Lim, Pre, Pim, Bre, Bim, Cri, ls);
    k1_rowfft    <<<128,  TPB1>>>();
    k2_ifft_cols <<<128,  TPB2>>>();
    k3_fwd_cols  <<<256,  TPB3>>>(u);
    k4_mega      <<<256,  TPB4>>>();
    k5_inv_cols  <<<256,  TPB5>>>(u, Dp, out);
}

// round 8
// speedup vs baseline: 2.6162x; 1.1474x over previous
#include <cuda_runtime.h>

// S4 DPLR layer, round 8: bank-conflict-engineered radix-8 FFT layouts
// (every smem access <=2-way = LDS.64 floor), k2+k3 fused (no dK round
// trip), 5 kernels total.
//
// Pipeline:
//  k0 : DPLR generator -> dA[k1*512 + m]  (j = k1 + 512 m)
//  k1 : row IFFT512 of dA + four-step twiddle -> dB     [IFFT_L pass 1]
//  k23: per column m: IFFT512 (-> K), then forward FFT512 of
//       z = u + i*K for c = m and c = m+512, fwd twiddle -> dA
//  k4 : MEGA: paired rows (k1, 512-k1): fwd FFT1024 x2 (radix-2 split),
//       Hermitian split U,Kd + multiply, inv FFT1024 x2, twiddle -> dB
//  k5 : column IFFT512 of dB, out[n] = Re/2L + D*u[n]  (first L only)

#define L_SIZE   262144   // 2^18
#define N2L      524288   // 2^19
#define PI2      6.283185307179586f
#define RT2      0.70710678118654752f
#define CH       544      // padded smem chunk per 512-pt FFT (float2 units)

__device__ float2 dA[N2L];    // 4 MB scratch
__device__ float2 dB[N2L];    // 4 MB scratch

static __device__ __forceinline__ float2 cmul(float2 a, float2 b) {
    return make_float2(a.x*b.x - a.y*b.y, a.x*b.y + a.y*b.x);
}
static __device__ __forceinline__ float2 cadd(float2 a, float2 b) {
    return make_float2(a.x + b.x, a.y + b.y);
}
static __device__ __forceinline__ float2 csub(float2 a, float2 b) {
    return make_float2(a.x - b.x, a.y - b.y);
}
static __device__ __forceinline__ float2 cfma(float2 a, float2 b, float2 acc) {
    acc.x = fmaf(a.x, b.x, fmaf(-a.y, b.y, acc.x));
    acc.y = fmaf(a.x, b.y, fmaf( a.y, b.x, acc.y));
    return acc;
}

// tw[k] = exp(-2*pi*i*k/len), k in [0, cnt)
template<int NT>
static __device__ __forceinline__ void fill_tw(float2* tw, int cnt, int len) {
    for (int k = threadIdx.x; k < cnt; k += NT) {
        float s, c;
        sincospif(-2.0f * (float)k / (float)len, &s, &c);
        tw[k] = make_float2(c, s);
    }
}

// exp(sgn * 2*pi*i * mm / n), mm in [0, n). Centered arg -> __sincosf safe.
static __device__ __forceinline__ float2 twiddle_c(int mm, int n, float sgn) {
    int tt = mm - ((mm >= (n >> 1)) ? n : 0);
    float ang = sgn * (PI2 / (float)n) * (float)tt;
    float s, c; __sincosf(ang, &s, &c);
    return make_float2(c, s);
}

template<int SIGN>
static __device__ __forceinline__ float2 twl(const float2* tw, int idx) {
    float2 w = tw[idx];
    if (SIGN > 0) w.y = -w.y;
    return w;
}
template<int SIGN>
static __device__ __forceinline__ float2 mulpmi(float2 a) {
    return (SIGN < 0) ? make_float2(a.y, -a.x) : make_float2(-a.y, a.x);
}
template<int SIGN>
static __device__ __forceinline__ float2 mulw81(float2 a) {
    return (SIGN < 0) ? make_float2(RT2*(a.x + a.y), RT2*(a.y - a.x))
                      : make_float2(RT2*(a.x - a.y), RT2*(a.x + a.y));
}
template<int SIGN>
static __device__ __forceinline__ float2 mulw83(float2 a) {
    return (SIGN < 0) ? make_float2(RT2*(a.y - a.x), RT2*(-a.x - a.y))
                      : make_float2(RT2*(-a.x - a.y), RT2*(a.x - a.y));
}

// 8-point FFT in registers, natural order in/out. SIGN=-1 fwd, +1 inv.
template<int SIGN>
static __device__ __forceinline__ void fft8(float2 v[8]) {
    float2 t0 = cadd(v[0], v[4]), t1 = csub(v[0], v[4]);
    float2 t2 = cadd(v[2], v[6]), t3 = mulpmi<SIGN>(csub(v[2], v[6]));
    float2 E0 = cadd(t0, t2), E1 = cadd(t1, t3);
    float2 E2 = csub(t0, t2), E3 = csub(t1, t3);
    float2 u0 = cadd(v[1], v[5]), u1 = csub(v[1], v[5]);
    float2 u2 = cadd(v[3], v[7]), u3 = mulpmi<SIGN>(csub(v[3], v[7]));
    float2 O0 = cadd(u0, u2), O1 = cadd(u1, u3);
    float2 O2 = csub(u0, u2), O3 = csub(u1, u3);
    O1 = mulw81<SIGN>(O1);
    O2 = mulpmi<SIGN>(O2);
    O3 = mulw83<SIGN>(O3);
    v[0] = cadd(E0, O0); v[4] = csub(E0, O0);
    v[1] = cadd(E1, O1); v[5] = csub(E1, O1);
    v[2] = cadd(E2, O2); v[6] = csub(E2, O2);
    v[3] = cadd(E3, O3); v[7] = csub(E3, O3);
}

// 512-pt FFT, 64 threads per FFT (l in [0,64)), 8 points/thread, chunk f
// at offset f*CH in both buffers. Natural input in bufA[f*CH + 0..511],
// natural output in bufB[f*CH + 0..511]; bufA clobbered. All threads of the
// block MUST call (barriers inside); `active` masks the work only.
// Layouts: phase1 out bufB: [k0]-stride 66 (addr 66*k0 + n1*8 + n0);
//          phase2 out bufA: [n0]-stride 68 (addr 68*n0 + 8*k1 + k0).
// Every warp access is <=2-way bank conflict; phase-3 fully conflict-free.
// Decomposition n = 64*n2 + 8*n1 + n0 -> k = k0 + 8*k1 + 64*k2.
template<int SIGN>
static __device__ __forceinline__ void fft512x(
    float2* bufA, float2* bufB, int f, int l, const float2* tw, bool active)
{
    const int base = f * CH;
    float2 v[8];
    if (active) {
        #pragma unroll
        for (int e = 0; e < 8; ++e) v[e] = bufA[base + l + 64*e];
        fft8<SIGN>(v);                               // over n2 -> k0
        const int n1 = l >> 3;
        #pragma unroll
        for (int k0 = 1; k0 < 8; ++k0)               // W64^{n1 k0}
            v[k0] = cmul(v[k0], twl<SIGN>(tw, 8 * n1 * k0));
        #pragma unroll
        for (int k0 = 0; k0 < 8; ++k0) bufB[base + 66*k0 + l] = v[k0];
    }
    __syncthreads();
    {
        const int k0 = l & 7, n0 = l >> 3;
        if (active) {
            #pragma unroll
            for (int n1 = 0; n1 < 8; ++n1) v[n1] = bufB[base + 66*k0 + 8*n1 + n0];
            fft8<SIGN>(v);                           // over n1 -> k1
            #pragma unroll
            for (int k1 = 0; k1 < 8; ++k1)           // W512^{n0 (k0 + 8 k1)}
                v[k1] = cmul(v[k1], twl<SIGN>(tw, n0 * (k0 + 8*k1)));
            #pragma unroll
            for (int k1 = 0; k1 < 8; ++k1) bufA[base + 68*n0 + 8*k1 + k0] = v[k1];
        }
    }
    __syncthreads();
    if (active) {
        #pragma unroll
        for (int n0 = 0; n0 < 8; ++n0) v[n0] = bufA[base + 68*n0 + l];
        fft8<SIGN>(v);                               // over n0 -> k2
        #pragma unroll
        for (int k2 = 0; k2 < 8; ++k2) bufB[base + 64*k2 + l] = v[k2];
    }
    __syncthreads();
}

// ---------------------------------------------------------------------------
// k0: DPLR generator, grid=1024 x 256. 8 rows (k1, per warp) x 32 cols (m,
//     per lane) -> coalesced stores. Omega via sincosf (keeps 1+Omega != 0
//     at Nyquist, matching the f32 reference). Per-element reciprocals
//     (magnitudes reach ~2e21; batched products overflow float).
// ---------------------------------------------------------------------------
#define TPB0 256
__global__ void k0_gen(const float* __restrict__ Lre, const float* __restrict__ Lim,
                       const float* __restrict__ Pre, const float* __restrict__ Pim,
                       const float* __restrict__ Bre, const float* __restrict__ Bim,
                       const float* __restrict__ Cri, const float* __restrict__ ls) {
    __shared__ float  sLre[64], sLim[64];
    __shared__ float2 sv0[64], sv1[64], sv2[64], sv3[64];
    const int t = threadIdx.x;
    if (t < 64) {
        float2 Pv = make_float2(Pre[t], Pim[t]);
        float2 Bv = make_float2(Bre[t], Bim[t]);
        float2 Cj = make_float2(Cri[2*t], -Cri[2*t+1]);   // conj(C)
        float2 Pj = make_float2(Pv.x, -Pv.y);             // conj(P) (Q = P)
        sLre[t] = Lre[t]; sLim[t] = Lim[t];
        sv0[t] = cmul(Cj, Bv); sv1[t] = cmul(Cj, Pv);
        sv2[t] = cmul(Pj, Bv); sv3[t] = cmul(Pj, Pv);
    }
    __syncthreads();

    const int b = blockIdx.x;
    const int k1 = (b & 63) * 8 + (t >> 5);
    const int m  = (b >> 6) * 32 + (t & 31);
    const int j  = k1 + (m << 9);
    const float step = expf(ls[0]);

    float ang = -PI2 * ((float)j / (float)L_SIZE);
    float sn, cs; sincosf(ang, &sn, &cs);          // Omega = cs + i*sn
    float2 onem = make_float2(1.f - cs, -sn);
    float2 onep = make_float2(1.f + cs,  sn);
    float invp = 1.f / (onep.x*onep.x + onep.y*onep.y);
    float2 cc = make_float2(2.f*onep.x*invp, -2.f*onep.y*invp);  // 2/(1+Om)
    float2 qv = cmul(onem, make_float2(onep.x, -onep.y));
    float sfac = (2.f / step) * invp;
    float gx = qv.x * sfac, gy = qv.y * sfac;

    float2 k00 = {0,0}, k01 = {0,0}, k10 = {0,0}, k11 = {0,0};
    #pragma unroll
    for (int n = 0; n < 64; ++n) {
        float dx = gx - sLre[n], dy = gy - sLim[n];
        float inv = 1.f / (dx*dx + dy*dy);
        float2 r = make_float2(dx*inv, -dy*inv);   // 1/(g - Lambda_n)
        k00 = cfma(r, sv0[n], k00);
        k01 = cfma(r, sv1[n], k01);
        k10 = cfma(r, sv2[n], k10);
        k11 = cfma(r, sv3[n], k11);
    }
    float2 den = make_float2(1.f + k11.x, k11.y);
    float invd = 1.f / (den.x*den.x + den.y*den.y);
    float2 num = cmul(k01, k10);
    float2 tq2 = cmul(num, make_float2(den.x*invd, -den.y*invd));
    float2 at  = cmul(cc, make_float2(k00.x - tq2.x, k00.y - tq2.y));

    dA[k1 * 512 + m] = at;
}

// ---------------------------------------------------------------------------
// k1: IFFT_L row pass (2 rows/block, TPB=128) + twiddle -> dB. grid=256
// ---------------------------------------------------------------------------
#define TPB1 128
__global__ void k1_rowfft() {
    __shared__ float2 sa[2*CH], sb[2*CH], tw[512];
    fill_tw<TPB1>(tw, 512, 512);
    const int row0 = blockIdx.x * 2;
    const int t = threadIdx.x;
    for (int i = t; i < 1024; i += TPB1) {
        int g = i >> 9, m = i & 511;
        sa[g*CH + m] = dA[(row0 + g) * 512 + m];
    }
    __syncthreads();
    fft512x<+1>(sa, sb, t >> 6, t & 63, tw, true);
    for (int i = t; i < 1024; i += TPB1) {
        int g = i >> 9, m = i & 511;
        int kk = row0 + g;
        int mm = (m * kk) & (L_SIZE - 1);
        dB[kk * 512 + m] = cmul(sb[g*CH + m], twiddle_c(mm, L_SIZE, 1.0f));
    }
}

// ---------------------------------------------------------------------------
// k23 FUSED: columns m0, m0+1 (grid=256, TPB=256).
//   Phase A: IFFT512 of dB column m (2 FFTs, threads<128) -> K[p] (natural,
//            in sb, scaled by 1/L at use).
//   Phase B: z = u + i*K for columns c = m and c = m+512 of the 2L matrix
//            (z[rr], rr<256; K[2rr+half] supplies column half). 4 fwd FFTs,
//            + fwd four-step twiddle, write dA[k1*1024 + c].
// ---------------------------------------------------------------------------
#define TPB23 256
__global__ void k23_cols(const float* __restrict__ u) {
    __shared__ float2 sa[4*CH], sb[4*CH], tw[512];
    fill_tw<TPB23>(tw, 512, 512);
    const int m0 = blockIdx.x * 2;
    const int t = threadIdx.x;
    // phase A load: 2 columns of dB (512x512 matrix)
    for (int i = t; i < 1024; i += TPB23) {
        int p = i >> 1, f = i & 1;
        sa[f*CH + p] = dB[p * 512 + m0 + f];
    }
    __syncthreads();
    fft512x<+1>(sa, sb, t >> 6, t & 63, tw, t < 128);
    // K[p] (col m0+f) = sb[f*CH + p].x * invL   (sb chunks 0,1)
    const float invL = 1.0f / (float)L_SIZE;
    // build z into sa chunks 0..3: chunk fp = half*2 + f -> column c
    for (int i = t; i < 2048; i += TPB23) {
        int fp = i >> 9, rr = i & 511;
        int half = fp >> 1, f = fp & 1;
        float2 z = make_float2(0.f, 0.f);
        if (rr < 256) {
            int c = m0 + f + half * 512;
            float kv = sb[f*CH + 2*rr + half].x * invL;
            z = make_float2(u[rr * 1024 + c], kv);
        }
        sa[fp*CH + rr] = z;
    }
    __syncthreads();
    fft512x<-1>(sa, sb, t >> 6, t & 63, tw, true);
    for (int i = t; i < 2048; i += TPB23) {
        int fp = i & 3, k1 = i >> 2;
        int half = fp >> 1, f = fp & 1;
        int c = m0 + f + half * 512;
        int mm = (c * k1) & (N2L - 1);
        dA[k1 * 1024 + c] = cmul(sb[fp*CH + k1], twiddle_c(mm, N2L, -1.0f));
    }
}

// ---------------------------------------------------------------------------
// k4 MEGA: paired rows (k1, 512-k1); block 0 takes self-paired rows {0,256}.
//   FFT1024 as radix-2 split: X[2r+h] = FFT512 of (a +/- b [*W1024^m]).
//   Chunk fp = slot*2 + h holds Z[2r+h] of row slot. Hermitian pointwise,
//   2x IFFT512 per slot, combine, inv twiddle -> dB. grid=256, TPB=256.
// ---------------------------------------------------------------------------
#define TPB4 256
__global__ void k4_mega() {
    __shared__ float2 sa[4*CH], sb[4*CH], tw[512], twh[512];
    fill_tw<TPB4>(tw, 512, 512);
    fill_tw<TPB4>(twh, 512, 1024);      // W1024^m
    const int b = blockIdx.x;
    const int rowA = b;
    const int rowB = (b == 0) ? 256 : 512 - b;
    const int t = threadIdx.x;

    // raw load into sb (slot-major natural, 1024 per slot)
    for (int i = t; i < 2048; i += TPB4) {
        int slot = i >> 10, m = i & 1023;
        int row = slot ? rowB : rowA;
        sb[slot * 1024 + m] = dA[row * 1024 + m];
    }
    __syncthreads();
    // radix-2 pre-stage into chunks: fp = slot*2 + h
    for (int i = t; i < 1024; i += TPB4) {
        int slot = i >> 9, m = i & 511;
        float2 a = sb[slot * 1024 + m];
        float2 c = sb[slot * 1024 + m + 512];
        sa[(slot*2 + 0)*CH + m] = cadd(a, c);
        sa[(slot*2 + 1)*CH + m] = cmul(csub(a, c), twh[m]);
    }
    __syncthreads();
    fft512x<-1>(sa, sb, t >> 6, t & 63, tw, true);
    // sb chunk fp, pos r  <->  Z[2r + (fp&1)] of row slot = fp>>1
    for (int i = t; i < 2048; i += TPB4) {
        int fp = i >> 9, r = i & 511;
        int slot = fp >> 1, h = fp & 1;
        int k = 2*r + h;
        int pslot, pk;
        if (b == 0) {
            pslot = slot;
            pk = slot ? (1023 - k) : ((1024 - k) & 1023);
        } else {
            pslot = 1 - slot;
            pk = 1023 - k;
        }
        float2 Zv = sb[fp*CH + r];
        float2 Zp = sb[(pslot*2 + (pk & 1))*CH + (pk >> 1)];
        float2 U  = make_float2(0.5f * (Zv.x + Zp.x),  0.5f * (Zv.y - Zp.y));
        float2 Kd = make_float2(0.5f * (Zv.y + Zp.y), -0.5f * (Zv.x - Zp.x));
        sa[fp*CH + r] = cmul(U, Kd);
    }
    __syncthreads();
    fft512x<+1>(sa, sb, t >> 6, t & 63, tw, true);
    // combine halves + inverse four-step twiddle + store
    for (int i = t; i < 1024; i += TPB4) {
        int slot = i >> 9, m = i & 511;
        float2 E = sb[(slot*2 + 0)*CH + m];
        float2 O = sb[(slot*2 + 1)*CH + m];
        float2 Vm = make_float2(twh[m].x, -twh[m].y);   // conj
        float2 w  = cmul(Vm, O);
        float2 y0 = cadd(E, w);
        float2 y1 = csub(E, w);
        int kk = slot ? rowB : rowA;
        int mm0 = (m * kk) & (N2L - 1);
        int mm1 = ((m + 512) * kk) & (N2L - 1);
        dB[kk * 1024 + m]       = cmul(y0, twiddle_c(mm0, N2L, 1.0f));
        dB[kk * 1024 + m + 512] = cmul(y1, twiddle_c(mm1, N2L, 1.0f));
    }
}

// ---------------------------------------------------------------------------
// k5: inverse column FFTs (4 cols/block); out[n] = Re/2L + D*u[n],
//     only first 256 rows (n < L). grid=256
// ---------------------------------------------------------------------------
#define TPB5 256
__global__ void k5_inv_cols(const float* __restrict__ u, const float* __restrict__ Dp,
                            float* __restrict__ out) {
    __shared__ float2 sa[4*CH], sb[4*CH], tw[512];
    fill_tw<TPB5>(tw, 512, 512);
    const int c0 = blockIdx.x * 4;
    const int t = threadIdx.x;
    for (int i = t; i < 2048; i += TPB5) {
        int g = i & 3, rr = i >> 2;
        sa[g*CH + rr] = dB[rr * 1024 + c0 + g];
    }
    __syncthreads();
    fft512x<+1>(sa, sb, t >> 6, t & 63, tw, true);
    const float sc = 1.0f / (float)N2L;
    const float Dv = Dp[0];
    for (int i = t; i < 1024; i += TPB5) {
        int g = i & 3, p = i >> 2;
        int n = p * 1024 + c0 + g;
        out[n] = fmaf(Dv, u[n], sb[g*CH + p].x * sc);
    }
}

// ---------------------------------------------------------------------------
extern "C" void kernel_launch(void* const* d_in, const int* in_sizes, int n_in,
                              void* d_out, int out_size) {
    (void)in_sizes; (void)n_in; (void)out_size;
    const float* u   = (const float*)d_in[0];
    const float* Lre = (const float*)d_in[1];
    const float* Lim = (const float*)d_in[2];
    const float* Pre = (const float*)d_in[3];
    const float* Pim = (const float*)d_in[4];
    const float* Bre = (const float*)d_in[5];
    const float* Bim = (const float*)d_in[6];
    const float* Cri = (const float*)d_in[7];
    const float* Dp  = (const float*)d_in[8];
    const float* ls  = (const float*)d_in[9];
    float* out = (float*)d_out;

    k0_gen      <<<1024, TPB0>>>(Lre, Lim, Pre, Pim, Bre, Bim, Cri, ls);
    k1_rowfft   <<<256,  TPB1>>>();
    k23_cols    <<<256,  TPB23>>>(u);
    k4_mega     <<<256,  TPB4>>>();
    k5_inv_cols <<<256,  TPB5>>>(u, Dp, out);
}

// round 9
// speedup vs baseline: 2.8096x; 1.0739x over previous
#include <cuda_runtime.h>

// S4 DPLR layer, round 9: global twiddle tables (no per-block trig),
// float4-vectorized staging, k23 u-prefetch overlap, k0 scaled batched
// reciprocals. FFT cores identical to verified round-8 (conflict-engineered
// radix-8, <=2-way on every smem access).
//
// Pipeline:
//  k0 : DPLR generator -> dA[k1*512 + m]; blocks 0,1 fill twiddle tables
//  k1 : row IFFT512 of dA + four-step twiddle -> dB     [IFFT_L pass 1]
//  k23: per column pair: IFFT512 (-> K), then forward FFT512 of
//       z = u + i*K for c = m and c = m+512, fwd twiddle -> dA
//  k4 : MEGA: paired rows (k1, 512-k1): fwd FFT1024 x2 (radix-2 split),
//       Hermitian split U,Kd + multiply, inv FFT1024 x2, twiddle -> dB
//  k5 : column IFFT512 of dB, out[n] = Re/2L + D*u[n]  (first L only)

#define L_SIZE   262144   // 2^18
#define N2L      524288   // 2^19
#define PI2      6.283185307179586f
#define RT2      0.70710678118654752f
#define CH       544      // padded smem chunk per 512-pt FFT (float2 units)

__device__ float4 dA4_[N2L/2];    // 4 MB scratch (float4-backed: 16B aligned)
__device__ float4 dB4_[N2L/2];    // 4 MB scratch
#define dA ((float2*)dA4_)
#define dB ((float2*)dB4_)
__device__ float2 gtw512g[512];   // exp(-2pi i k/512)
__device__ float2 gtw1024g[512];  // exp(-2pi i k/1024), k<512

static __device__ __forceinline__ float2 cmul(float2 a, float2 b) {
    return make_float2(a.x*b.x - a.y*b.y, a.x*b.y + a.y*b.x);
}
static __device__ __forceinline__ float2 cadd(float2 a, float2 b) {
    return make_float2(a.x + b.x, a.y + b.y);
}
static __device__ __forceinline__ float2 csub(float2 a, float2 b) {
    return make_float2(a.x - b.x, a.y - b.y);
}
static __device__ __forceinline__ float2 cfma(float2 a, float2 b, float2 acc) {
    acc.x = fmaf(a.x, b.x, fmaf(-a.y, b.y, acc.x));
    acc.y = fmaf(a.x, b.y, fmaf( a.y, b.x, acc.y));
    return acc;
}

// exp(sgn * 2*pi*i * mm / n), mm in [0, n). Centered arg -> __sincosf safe.
static __device__ __forceinline__ float2 twiddle_c(int mm, int n, float sgn) {
    int tt = mm - ((mm >= (n >> 1)) ? n : 0);
    float ang = sgn * (PI2 / (float)n) * (float)tt;
    float s, c; __sincosf(ang, &s, &c);
    return make_float2(c, s);
}

template<int SIGN>
static __device__ __forceinline__ float2 twl(const float2* tw, int idx) {
    float2 w = tw[idx];
    if (SIGN > 0) w.y = -w.y;
    return w;
}
template<int SIGN>
static __device__ __forceinline__ float2 mulpmi(float2 a) {
    return (SIGN < 0) ? make_float2(a.y, -a.x) : make_float2(-a.y, a.x);
}
template<int SIGN>
static __device__ __forceinline__ float2 mulw81(float2 a) {
    return (SIGN < 0) ? make_float2(RT2*(a.x + a.y), RT2*(a.y - a.x))
                      : make_float2(RT2*(a.x - a.y), RT2*(a.x + a.y));
}
template<int SIGN>
static __device__ __forceinline__ float2 mulw83(float2 a) {
    return (SIGN < 0) ? make_float2(RT2*(a.y - a.x), RT2*(-a.x - a.y))
                      : make_float2(RT2*(-a.x - a.y), RT2*(a.x - a.y));
}

// 8-point FFT in registers, natural order in/out. SIGN=-1 fwd, +1 inv.
template<int SIGN>
static __device__ __forceinline__ void fft8(float2 v[8]) {
    float2 t0 = cadd(v[0], v[4]), t1 = csub(v[0], v[4]);
    float2 t2 = cadd(v[2], v[6]), t3 = mulpmi<SIGN>(csub(v[2], v[6]));
    float2 E0 = cadd(t0, t2), E1 = cadd(t1, t3);
    float2 E2 = csub(t0, t2), E3 = csub(t1, t3);
    float2 u0 = cadd(v[1], v[5]), u1 = csub(v[1], v[5]);
    float2 u2 = cadd(v[3], v[7]), u3 = mulpmi<SIGN>(csub(v[3], v[7]));
    float2 O0 = cadd(u0, u2), O1 = cadd(u1, u3);
    float2 O2 = csub(u0, u2), O3 = csub(u1, u3);
    O1 = mulw81<SIGN>(O1);
    O2 = mulpmi<SIGN>(O2);
    O3 = mulw83<SIGN>(O3);
    v[0] = cadd(E0, O0); v[4] = csub(E0, O0);
    v[1] = cadd(E1, O1); v[5] = csub(E1, O1);
    v[2] = cadd(E2, O2); v[6] = csub(E2, O2);
    v[3] = cadd(E3, O3); v[7] = csub(E3, O3);
}

// 512-pt FFT, 64 threads per FFT (l in [0,64)), 8 points/thread, chunk f at
// offset f*CH in both buffers. Natural input bufA[f*CH+0..511], natural
// output bufB[f*CH+0..511]; bufA clobbered. All block threads MUST call
// (barriers inside); `active` masks work only.
// Layouts: phase1 out: [k0]-stride 66; phase2 out: [n0]-stride 68.
// Every warp access <=2-way conflict. n = 64 n2 + 8 n1 + n0 -> k = k0+8k1+64k2.
template<int SIGN>
static __device__ __forceinline__ void fft512x(
    float2* bufA, float2* bufB, int f, int l, const float2* tw, bool active)
{
    const int base = f * CH;
    float2 v[8];
    if (active) {
        #pragma unroll
        for (int e = 0; e < 8; ++e) v[e] = bufA[base + l + 64*e];
        fft8<SIGN>(v);                               // over n2 -> k0
        const int n1 = l >> 3;
        #pragma unroll
        for (int k0 = 1; k0 < 8; ++k0)               // W64^{n1 k0}
            v[k0] = cmul(v[k0], twl<SIGN>(tw, 8 * n1 * k0));
        #pragma unroll
        for (int k0 = 0; k0 < 8; ++k0) bufB[base + 66*k0 + l] = v[k0];
    }
    __syncthreads();
    {
        const int k0 = l & 7, n0 = l >> 3;
        if (active) {
            #pragma unroll
            for (int n1 = 0; n1 < 8; ++n1) v[n1] = bufB[base + 66*k0 + 8*n1 + n0];
            fft8<SIGN>(v);                           // over n1 -> k1
            #pragma unroll
            for (int k1 = 0; k1 < 8; ++k1)           // W512^{n0 (k0 + 8 k1)}
                v[k1] = cmul(v[k1], twl<SIGN>(tw, n0 * (k0 + 8*k1)));
            #pragma unroll
            for (int k1 = 0; k1 < 8; ++k1) bufA[base + 68*n0 + 8*k1 + k0] = v[k1];
        }
    }
    __syncthreads();
    if (active) {
        #pragma unroll
        for (int n0 = 0; n0 < 8; ++n0) v[n0] = bufA[base + 68*n0 + l];
        fft8<SIGN>(v);                               // over n0 -> k2
        #pragma unroll
        for (int k2 = 0; k2 < 8; ++k2) bufB[base + 64*k2 + l] = v[k2];
    }
    __syncthreads();
}

// ---------------------------------------------------------------------------
// k0: DPLR generator, grid=1024 x 256. 8 rows (k1, per warp) x 32 cols (m,
//     per lane) -> coalesced stores. Omega via sincosf (keeps 1+Omega != 0
//     at Nyquist, matching the f32 reference). Pair-batched reciprocals with
//     2^-24 scaling: a in [0.25, 2.6e21] -> scaled product in [2e-16, 2.4e28],
//     no overflow. Blocks 0,1 also fill the global twiddle tables.
// ---------------------------------------------------------------------------
#define TPB0 256
__global__ void k0_gen(const float* __restrict__ Lre, const float* __restrict__ Lim,
                       const float* __restrict__ Pre, const float* __restrict__ Pim,
                       const float* __restrict__ Bre, const float* __restrict__ Bim,
                       const float* __restrict__ Cri, const float* __restrict__ ls) {
    __shared__ float  sLre[64], sLim[64];
    __shared__ float2 sv0[64], sv1[64], sv2[64], sv3[64];
    const int t = threadIdx.x;
    const int b = blockIdx.x;
    if (b == 0) {
        for (int k = t; k < 512; k += TPB0) {
            float s, c; sincospif(-2.0f * (float)k / 512.0f, &s, &c);
            gtw512g[k] = make_float2(c, s);
        }
    } else if (b == 1) {
        for (int k = t; k < 512; k += TPB0) {
            float s, c; sincospif(-2.0f * (float)k / 1024.0f, &s, &c);
            gtw1024g[k] = make_float2(c, s);
        }
    }
    if (t < 64) {
        float2 Pv = make_float2(Pre[t], Pim[t]);
        float2 Bv = make_float2(Bre[t], Bim[t]);
        float2 Cj = make_float2(Cri[2*t], -Cri[2*t+1]);   // conj(C)
        float2 Pj = make_float2(Pv.x, -Pv.y);             // conj(P) (Q = P)
        sLre[t] = Lre[t]; sLim[t] = Lim[t];
        sv0[t] = cmul(Cj, Bv); sv1[t] = cmul(Cj, Pv);
        sv2[t] = cmul(Pj, Bv); sv3[t] = cmul(Pj, Pv);
    }
    __syncthreads();

    const int k1 = (b & 63) * 8 + (t >> 5);
    const int m  = (b >> 6) * 32 + (t & 31);
    const int j  = k1 + (m << 9);
    const float step = expf(ls[0]);

    float ang = -PI2 * ((float)j / (float)L_SIZE);
    float sn, cs; sincosf(ang, &sn, &cs);          // Omega = cs + i*sn
    float2 onem = make_float2(1.f - cs, -sn);
    float2 onep = make_float2(1.f + cs,  sn);
    float invp = 1.f / (onep.x*onep.x + onep.y*onep.y);
    float2 cc = make_float2(2.f*onep.x*invp, -2.f*onep.y*invp);  // 2/(1+Om)
    float2 qv = cmul(onem, make_float2(onep.x, -onep.y));
    float sfac = (2.f / step) * invp;
    float gx = qv.x * sfac, gy = qv.y * sfac;

    const float S = 5.9604644775390625e-8f;        // 2^-24
    float2 k00 = {0,0}, k01 = {0,0}, k10 = {0,0}, k11 = {0,0};
    #pragma unroll
    for (int q = 0; q < 32; ++q) {
        const int n = 2*q;
        float dx0 = gx - sLre[n],   dy0 = gy - sLim[n];
        float dx1 = gx - sLre[n+1], dy1 = gy - sLim[n+1];
        float a0 = fmaf(dx0, dx0, dy0*dy0) * S;
        float a1 = fmaf(dx1, dx1, dy1*dy1) * S;
        float tq = 1.f / (a0 * a1);
        float i0 = a1 * tq * S;                    // = 1/(dx0^2+dy0^2)
        float i1 = a0 * tq * S;
        float2 r0 = make_float2(dx0*i0, -dy0*i0);
        float2 r1 = make_float2(dx1*i1, -dy1*i1);
        k00 = cfma(r0, sv0[n],   k00); k01 = cfma(r0, sv1[n],   k01);
        k10 = cfma(r0, sv2[n],   k10); k11 = cfma(r0, sv3[n],   k11);
        k00 = cfma(r1, sv0[n+1], k00); k01 = cfma(r1, sv1[n+1], k01);
        k10 = cfma(r1, sv2[n+1], k10); k11 = cfma(r1, sv3[n+1], k11);
    }
    float2 den = make_float2(1.f + k11.x, k11.y);
    float invd = 1.f / (den.x*den.x + den.y*den.y);
    float2 num = cmul(k01, k10);
    float2 tq2 = cmul(num, make_float2(den.x*invd, -den.y*invd));
    float2 at  = cmul(cc, make_float2(k00.x - tq2.x, k00.y - tq2.y));

    dA[k1 * 512 + m] = at;
}

// ---------------------------------------------------------------------------
// k1: IFFT_L row pass (2 rows/block, TPB=128) + twiddle -> dB. grid=256
// ---------------------------------------------------------------------------
#define TPB1 128
__global__ void k1_rowfft() {
    __shared__ __align__(16) float2 sa[2*CH], sb[2*CH];
    __shared__ float2 tw[512];
    const int t = threadIdx.x;
    for (int i = t; i < 512; i += TPB1) tw[i] = gtw512g[i];
    const int row0 = blockIdx.x * 2;
    const float4* src = (const float4*)(dA + row0 * 512);
    for (int i = t; i < 512; i += TPB1) {
        int g = i >> 8, m2 = i & 255;
        float4 x = src[i];
        *(float4*)&sa[g*CH + 2*m2] = x;
    }
    __syncthreads();
    fft512x<+1>(sa, sb, t >> 6, t & 63, tw, true);
    for (int i = t; i < 512; i += TPB1) {
        int g = i >> 8, m2 = i & 255, m = 2*m2;
        int kk = row0 + g;
        float2 y0 = cmul(sb[g*CH + m],     twiddle_c((m*kk) & (L_SIZE-1),     L_SIZE, 1.0f));
        float2 y1 = cmul(sb[g*CH + m + 1], twiddle_c(((m+1)*kk) & (L_SIZE-1), L_SIZE, 1.0f));
        *(float4*)&dB[kk * 512 + m] = make_float4(y0.x, y0.y, y1.x, y1.y);
    }
}

// ---------------------------------------------------------------------------
// k23 FUSED: columns m0, m0+1 (grid=256, TPB=256).
//   Phase A: IFFT512 of dB cols (2 FFTs, threads<128) -> K; meanwhile
//            threads>=128 prefetch the strided u-gather into smem.
//   Phase B: z = u + i*K for c = m and c = m+512; 4 fwd FFTs + fwd twiddle
//            -> dA[k1*1024 + c].
// ---------------------------------------------------------------------------
#define TPB23 256
__global__ void k23_cols(const float* __restrict__ u) {
    __shared__ __align__(16) float2 sa[4*CH], sb[4*CH];
    __shared__ float2 tw[512];
    __shared__ float su[4*260];
    const int m0 = blockIdx.x * 2;
    const int t = threadIdx.x;
    for (int i = t; i < 512; i += TPB23) tw[i] = gtw512g[i];
    // phase A load: 2 columns of dB (512x512), 16B per row
    for (int i = t; i < 512; i += TPB23) {
        float4 x = *(const float4*)(dB + i * 512 + m0);
        sa[0*CH + i] = make_float2(x.x, x.y);
        sa[1*CH + i] = make_float2(x.z, x.w);
    }
    __syncthreads();
    // idle half prefetches u columns while phase A runs
    if (t >= 128) {
        for (int i = t - 128; i < 1024; i += 128) {
            int fp = i & 3, rr = i >> 2;
            int c = m0 + (fp & 1) + (fp >> 1) * 512;
            su[fp * 260 + rr] = u[rr * 1024 + c];
        }
    }
    fft512x<+1>(sa, sb, t >> 6, t & 63, tw, t < 128);
    // K[p] (col m0+f) = sb[f*CH + p].x * invL
    const float invL = 1.0f / (float)L_SIZE;
    for (int i = t; i < 2048; i += TPB23) {
        int fp = i >> 9, rr = i & 511;
        int half = fp >> 1, f = fp & 1;
        float2 z = make_float2(0.f, 0.f);
        if (rr < 256) {
            float kv = sb[f*CH + 2*rr + half].x * invL;
            z = make_float2(su[fp * 260 + rr], kv);
        }
        sa[fp*CH + rr] = z;
    }
    __syncthreads();
    fft512x<-1>(sa, sb, t >> 6, t & 63, tw, true);
    for (int i = t; i < 2048; i += TPB23) {
        int fp = i & 3, k1 = i >> 2;
        int half = fp >> 1, f = fp & 1;
        int c = m0 + f + half * 512;
        int mm = (c * k1) & (N2L - 1);
        dA[k1 * 1024 + c] = cmul(sb[fp*CH + k1], twiddle_c(mm, N2L, -1.0f));
    }
}

// ---------------------------------------------------------------------------
// k4 MEGA: paired rows (k1, 512-k1); block 0 takes self-paired rows {0,256}.
//   FFT1024 as radix-2 split: X[2r+h] = FFT512 of (a +/- b [*W1024^m]).
//   Chunk fp = slot*2 + h holds Z[2r+h] of row slot. Hermitian pointwise,
//   2x IFFT512 per slot, combine, inv twiddle -> dB. grid=256, TPB=256.
// ---------------------------------------------------------------------------
#define TPB4 256
__global__ void k4_mega() {
    __shared__ __align__(16) float2 sa[4*CH], sb[4*CH];
    __shared__ float2 tw[512], twh[512];
    const int t = threadIdx.x;
    for (int i = t; i < 512; i += TPB4) { tw[i] = gtw512g[i]; twh[i] = gtw1024g[i]; }
    const int b = blockIdx.x;
    const int rowA = b;
    const int rowB = (b == 0) ? 256 : 512 - b;

    // raw load into sb (slot-major natural, 1024 per slot), float4
    for (int i = t; i < 1024; i += TPB4) {
        int slot = i >> 9, m2 = i & 511;
        int row = slot ? rowB : rowA;
        float4 x = ((const float4*)(dA + row * 1024))[m2];
        *(float4*)&sb[slot * 1024 + 2*m2] = x;
    }
    __syncthreads();
    // radix-2 pre-stage into chunks: fp = slot*2 + h
    for (int i = t; i < 1024; i += TPB4) {
        int slot = i >> 9, m = i & 511;
        float2 a = sb[slot * 1024 + m];
        float2 c = sb[slot * 1024 + m + 512];
        sa[(slot*2 + 0)*CH + m] = cadd(a, c);
        sa[(slot*2 + 1)*CH + m] = cmul(csub(a, c), twh[m]);
    }
    __syncthreads();
    fft512x<-1>(sa, sb, t >> 6, t & 63, tw, true);
    // sb chunk fp, pos r  <->  Z[2r + (fp&1)] of row slot = fp>>1
    for (int i = t; i < 2048; i += TPB4) {
        int fp = i >> 9, r = i & 511;
        int slot = fp >> 1, h = fp & 1;
        int k = 2*r + h;
        int pslot, pk;
        if (b == 0) {
            pslot = slot;
            pk = slot ? (1023 - k) : ((1024 - k) & 1023);
        } else {
            pslot = 1 - slot;
            pk = 1023 - k;
        }
        float2 Zv = sb[fp*CH + r];
        float2 Zp = sb[(pslot*2 + (pk & 1))*CH + (pk >> 1)];
        float2 U  = make_float2(0.5f * (Zv.x + Zp.x),  0.5f * (Zv.y - Zp.y));
        float2 Kd = make_float2(0.5f * (Zv.y + Zp.y), -0.5f * (Zv.x - Zp.x));
        sa[fp*CH + r] = cmul(U, Kd);
    }
    __syncthreads();
    fft512x<+1>(sa, sb, t >> 6, t & 63, tw, true);
    // combine halves + inverse four-step twiddle + store (coalesced float2)
    for (int i = t; i < 1024; i += TPB4) {
        int slot = i >> 9, m = i & 511;
        float2 E = sb[(slot*2 + 0)*CH + m];
        float2 O = sb[(slot*2 + 1)*CH + m];
        float2 Vm = make_float2(twh[m].x, -twh[m].y);   // conj
        float2 w  = cmul(Vm, O);
        float2 y0 = cadd(E, w);
        float2 y1 = csub(E, w);
        int kk = slot ? rowB : rowA;
        int mm0 = (m * kk) & (N2L - 1);
        int mm1 = ((m + 512) * kk) & (N2L - 1);
        dB[kk * 1024 + m]       = cmul(y0, twiddle_c(mm0, N2L, 1.0f));
        dB[kk * 1024 + m + 512] = cmul(y1, twiddle_c(mm1, N2L, 1.0f));
    }
}

// ---------------------------------------------------------------------------
// k5: inverse column FFTs (4 cols/block); out[n] = Re/2L + D*u[n],
//     only first 256 rows (n < L). grid=256
// ---------------------------------------------------------------------------
#define TPB5 256
__global__ void k5_inv_cols(const float* __restrict__ u, const float* __restrict__ Dp,
                            float* __restrict__ out) {
    __shared__ __align__(16) float2 sa[4*CH], sb[4*CH];
    __shared__ float2 tw[512];
    const int c0 = blockIdx.x * 4;
    const int t = threadIdx.x;
    for (int i = t; i < 512; i += TPB5) tw[i] = gtw512g[i];
    for (int i = t; i < 1024; i += TPB5) {
        int rr = i >> 1, gg = i & 1;
        float4 x = ((const float4*)(dB + rr * 1024 + c0))[gg];
        sa[(2*gg  )*CH + rr] = make_float2(x.x, x.y);
        sa[(2*gg+1)*CH + rr] = make_float2(x.z, x.w);
    }
    __syncthreads();
    fft512x<+1>(sa, sb, t >> 6, t & 63, tw, true);
    const float sc = 1.0f / (float)N2L;
    const float Dv = Dp[0];
    for (int p = t; p < 256; p += TPB5) {
        float4 uu = *(const float4*)(u + p * 1024 + c0);
        float4 o;
        o.x = fmaf(Dv, uu.x, sb[0*CH + p].x * sc);
        o.y = fmaf(Dv, uu.y, sb[1*CH + p].x * sc);
        o.z = fmaf(Dv, uu.z, sb[2*CH + p].x * sc);
        o.w = fmaf(Dv, uu.w, sb[3*CH + p].x * sc);
        *(float4*)(out + p * 1024 + c0) = o;
    }
}

// ---------------------------------------------------------------------------
extern "C" void kernel_launch(void* const* d_in, const int* in_sizes, int n_in,
                              void* d_out, int out_size) {
    (void)in_sizes; (void)n_in; (void)out_size;
    const float* u   = (const float*)d_in[0];
    const float* Lre = (const float*)d_in[1];
    const float* Lim = (const float*)d_in[2];
    const float* Pre = (const float*)d_in[3];
    const float* Pim = (const float*)d_in[4];
    const float* Bre = (const float*)d_in[5];
    const float* Bim = (const float*)d_in[6];
    const float* Cri = (const float*)d_in[7];
    const float* Dp  = (const float*)d_in[8];
    const float* ls  = (const float*)d_in[9];
    float* out = (float*)d_out;

    k0_gen      <<<1024, TPB0>>>(Lre, Lim, Pre, Pim, Bre, Bim, Cri, ls);
    k1_rowfft   <<<256,  TPB1>>>();
    k23_cols    <<<256,  TPB23>>>(u);
    k4_mega     <<<256,  TPB4>>>();
    k5_inv_cols <<<256,  TPB5>>>(u, Dp, out);
}